// round 2
// baseline (speedup 1.0000x reference)
#include <cuda_runtime.h>
#include <math.h>

#define Bsz   16
#define CDIM  384
#define HH    56
#define WW    56
#define NTOK  3136          // 56*56
#define TOKS  (Bsz*NTOK)    // 50176
#define NHEAD 8
#define HDm   48
#define SPLIT 128
#define HID   1536
#define RR    192

// ---------------- scratch (device globals: no allocations allowed) ----------
// g_big is time-shared: qkv [TOKS*1152] (dead after attention) then h [TOKS*1536]
__device__ float g_big[(size_t)TOKS*HID];
__device__ float g_s1 [(size_t)Bsz*SPLIT*NTOK];
__device__ float g_s2 [(size_t)Bsz*SPLIT*NTOK];
__device__ float g_xf [(size_t)TOKS*CDIM];
__device__ float g_y  [(size_t)TOKS*CDIM];     // ln1 out, reused for ln2 out
__device__ float g_att[(size_t)TOKS*CDIM];     // attention out, reused for final
__device__ float g_xf2[(size_t)TOKS*CDIM];
__device__ float g_t1 [(size_t)TOKS*RR];
__device__ float g_t2 [(size_t)TOKS*RR];

// ---------------- depthwise 3x3 conv (correlation, SAME) --------------------
__global__ __launch_bounds__(256) void dwconv_kernel(
    const float* __restrict__ pA, long strideA,
    const float* __restrict__ pB, long strideB,
    const float* __restrict__ w, const float* __restrict__ bias,
    float* __restrict__ out)
{
    int idx = blockIdx.x * 256 + threadIdx.x;
    if (idx >= Bsz * SPLIT * NTOK) return;
    int n = idx % NTOK;
    int c = (idx / NTOK) % SPLIT;
    int b = idx / (NTOK * SPLIT);
    int hh = n / WW, ww = n % WW;
    const float* a  = pA + (size_t)b * strideA + (size_t)c * NTOK;
    const float* bb = pB + (size_t)b * strideB + (size_t)c * NTOK;
    float acc = bias[c];
#pragma unroll
    for (int i = 0; i < 3; i++) {
        int ih = hh + i - 1;
        if (ih < 0 || ih >= HH) continue;
#pragma unroll
        for (int j = 0; j < 3; j++) {
            int iw = ww + j - 1;
            if (iw < 0 || iw >= WW) continue;
            int off = ih * WW + iw;
            acc += w[c * 9 + i * 3 + j] * (a[off] + bb[off]);
        }
    }
    out[idx] = acc;
}

// ------------- assemble token-major x_flat from s0|s1|s2 (tiled transpose) --
__global__ __launch_bounds__(256) void assemble_kernel(const float* __restrict__ x)
{
    __shared__ float tile[32][33];
    int b = blockIdx.z, c0 = blockIdx.y * 32, n0 = blockIdx.x * 32;
    int tx = threadIdx.x, ty = threadIdx.y;
    const float* src;
    if (c0 < 128)      src = x    + ((size_t)b * CDIM  + c0)        * NTOK;
    else if (c0 < 256) src = g_s1 + ((size_t)b * SPLIT + (c0-128)) * NTOK;
    else               src = g_s2 + ((size_t)b * SPLIT + (c0-256)) * NTOK;
#pragma unroll
    for (int r = 0; r < 4; r++)
        tile[ty + r * 8][tx] = src[(size_t)(ty + r * 8) * NTOK + n0 + tx];
    __syncthreads();
#pragma unroll
    for (int r = 0; r < 4; r++)
        g_xf[((size_t)b * NTOK + n0 + ty + r * 8) * CDIM + c0 + tx] = tile[tx][ty + r * 8];
}

// ---------------- LayerNorm over C=384, one block per token -----------------
__global__ __launch_bounds__(128) void ln_kernel(
    const float* __restrict__ src, float* __restrict__ dst,
    const float* __restrict__ g, const float* __restrict__ bta)
{
    int tok = blockIdx.x;
    const float* r = src + (size_t)tok * CDIM;
    int tid = threadIdx.x;
    float v0 = r[tid], v1 = r[tid + 128], v2 = r[tid + 256];
    float s  = v0 + v1 + v2;
    float s2 = v0 * v0 + v1 * v1 + v2 * v2;
#pragma unroll
    for (int o = 16; o > 0; o >>= 1) {
        s  += __shfl_down_sync(0xFFFFFFFFu, s,  o);
        s2 += __shfl_down_sync(0xFFFFFFFFu, s2, o);
    }
    __shared__ float ss[4], ss2[4];
    int w = tid >> 5;
    if ((tid & 31) == 0) { ss[w] = s; ss2[w] = s2; }
    __syncthreads();
    if (tid == 0) {
        float a  = ss[0] + ss[1] + ss[2] + ss[3];
        float a2 = ss2[0] + ss2[1] + ss2[2] + ss2[3];
        float m  = a / CDIM;
        float var = a2 / CDIM - m * m;
        ss[0] = m; ss2[0] = rsqrtf(var + 1e-6f);
    }
    __syncthreads();
    float m = ss[0], rs = ss2[0];
    float* d = dst + (size_t)tok * CDIM;
    d[tid]       = (v0 - m) * rs * g[tid]       + bta[tid];
    d[tid + 128] = (v1 - m) * rs * g[tid + 128] + bta[tid + 128];
    d[tid + 256] = (v2 - m) * rs * g[tid + 256] + bta[tid + 256];
}

// ---------------- generic SGEMM: C[M,N] = A[M,K] @ B[K,N], epilogue ---------
// BM=128, BN=64, BK=16, 256 threads, per-thread 8x4. All dims exact multiples.
#define BM 128
#define BN 64
#define BK 16
__global__ __launch_bounds__(256) void sgemm(
    const float* __restrict__ A, const float* __restrict__ B, float* __restrict__ C,
    int M, int N, int K,
    const float* __restrict__ bias, const float* __restrict__ res, int do_gelu)
{
    __shared__ float As[BK][BM];
    __shared__ float Bs[BK][BN];
    int bx = blockIdx.x, by = blockIdx.y;
    int tid = threadIdx.x;
    int tx = tid & 15, ty = tid >> 4;
    const float* Ablk = A + (size_t)by * BM * K;
    const float* Bblk = B + bx * BN;
    float acc[8][4];
#pragma unroll
    for (int i = 0; i < 8; i++)
#pragma unroll
        for (int j = 0; j < 4; j++) acc[i][j] = 0.f;

    for (int kk = 0; kk < K; kk += BK) {
#pragma unroll
        for (int i = 0; i < 2; i++) {
            int f = tid + i * 256;
            int row = f >> 2, c4 = (f & 3) << 2;
            float4 v = *(const float4*)(Ablk + (size_t)row * K + kk + c4);
            As[c4 + 0][row] = v.x; As[c4 + 1][row] = v.y;
            As[c4 + 2][row] = v.z; As[c4 + 3][row] = v.w;
        }
        {
            int row = tid >> 4, c4 = (tid & 15) << 2;
            float4 v = *(const float4*)(Bblk + (size_t)(kk + row) * N + c4);
            *(float4*)&Bs[row][c4] = v;
        }
        __syncthreads();
#pragma unroll
        for (int k = 0; k < BK; k++) {
            float a[8], bb[4];
#pragma unroll
            for (int i = 0; i < 8; i++) a[i] = As[k][ty * 8 + i];
#pragma unroll
            for (int j = 0; j < 4; j++) bb[j] = Bs[k][tx * 4 + j];
#pragma unroll
            for (int i = 0; i < 8; i++)
#pragma unroll
                for (int j = 0; j < 4; j++) acc[i][j] += a[i] * bb[j];
        }
        __syncthreads();
    }

    int row0 = by * BM + ty * 8;
    int col0 = bx * BN + tx * 4;
#pragma unroll
    for (int i = 0; i < 8; i++) {
        float4 o;
        float t[4];
#pragma unroll
        for (int j = 0; j < 4; j++) {
            float v = acc[i][j];
            if (bias) v += bias[col0 + j];
            if (do_gelu) v = 0.5f * v * (1.f + erff(v * 0.70710678118f));
            if (res) v += res[(size_t)(row0 + i) * N + col0 + j];
            t[j] = v;
        }
        o.x = t[0]; o.y = t[1]; o.z = t[2]; o.w = t[3];
        *(float4*)(C + (size_t)(row0 + i) * N + col0) = o;
    }
}

// ---------------- XCA attention: one block per (head, batch) ----------------
__global__ __launch_bounds__(256) void attn_kernel()
{
    int h = blockIdx.x, b = blockIdx.y;
    __shared__ float q_s[48][65];
    __shared__ float k_s[48][65];
    __shared__ float attn_s[48][48];
    __shared__ float qn[48], kn[48];
    int tid = threadIdx.x;
    int td = tid >> 4, te = tid & 15;

    float acc[3][3];
#pragma unroll
    for (int i = 0; i < 3; i++)
#pragma unroll
        for (int j = 0; j < 3; j++) acc[i][j] = 0.f;
    float qssl = 0.f, kssl = 0.f;

    // Phase 1: Gram matrix Q.K^T plus per-row sumsqs, single pass over tokens
    for (int n0 = 0; n0 < NTOK; n0 += 64) {
        for (int i = tid; i < 48 * 64; i += 256) {
            int d = i % 48, nn = i / 48;
            size_t base = ((size_t)(b * NTOK + n0 + nn)) * 1152 + h * 48 + d;
            q_s[d][nn] = g_big[base];
            k_s[d][nn] = g_big[base + 384];
        }
        __syncthreads();
        if (tid < 48) {
            float t = 0.f;
#pragma unroll 8
            for (int nn = 0; nn < 64; nn++) { float v = q_s[tid][nn]; t += v * v; }
            qssl += t;
        } else if (tid >= 64 && tid < 112) {
            int d = tid - 64;
            float t = 0.f;
#pragma unroll 8
            for (int nn = 0; nn < 64; nn++) { float v = k_s[d][nn]; t += v * v; }
            kssl += t;
        }
#pragma unroll 4
        for (int nn = 0; nn < 64; nn++) {
            float qa0 = q_s[td * 3 + 0][nn], qa1 = q_s[td * 3 + 1][nn], qa2 = q_s[td * 3 + 2][nn];
            float kb0 = k_s[te * 3 + 0][nn], kb1 = k_s[te * 3 + 1][nn], kb2 = k_s[te * 3 + 2][nn];
            acc[0][0] += qa0 * kb0; acc[0][1] += qa0 * kb1; acc[0][2] += qa0 * kb2;
            acc[1][0] += qa1 * kb0; acc[1][1] += qa1 * kb1; acc[1][2] += qa1 * kb2;
            acc[2][0] += qa2 * kb0; acc[2][1] += qa2 * kb1; acc[2][2] += qa2 * kb2;
        }
        __syncthreads();
    }
    if (tid < 48)                 qn[tid]      = fmaxf(sqrtf(qssl), 1e-12f);
    if (tid >= 64 && tid < 112)   kn[tid - 64] = fmaxf(sqrtf(kssl), 1e-12f);
    __syncthreads();
#pragma unroll
    for (int i = 0; i < 3; i++)
#pragma unroll
        for (int j = 0; j < 3; j++)
            attn_s[td * 3 + i][te * 3 + j] = acc[i][j] / (qn[td * 3 + i] * kn[te * 3 + j]);
    __syncthreads();

    // softmax over e per row d
    if (tid < 48) {
        float mx = -1e30f;
#pragma unroll 8
        for (int e = 0; e < 48; e++) mx = fmaxf(mx, attn_s[tid][e]);
        float sm = 0.f;
#pragma unroll 8
        for (int e = 0; e < 48; e++) {
            float t = expf(attn_s[tid][e] - mx);
            attn_s[tid][e] = t; sm += t;
        }
        float inv = 1.f / sm;
#pragma unroll 8
        for (int e = 0; e < 48; e++) attn_s[tid][e] *= inv;
    }
    __syncthreads();

    // Phase 2: y = attn @ V, one token per thread per iteration
    for (int n0 = 0; n0 < NTOK; n0 += 256) {
        int n = n0 + tid;
        if (n >= NTOK) break;
        size_t base = ((size_t)(b * NTOK + n)) * 1152 + 768 + h * 48;
        float v[48];
#pragma unroll
        for (int i = 0; i < 12; i++) {
            float4 t = *(const float4*)(g_big + base + i * 4);
            v[i * 4 + 0] = t.x; v[i * 4 + 1] = t.y; v[i * 4 + 2] = t.z; v[i * 4 + 3] = t.w;
        }
        size_t ob = ((size_t)(b * NTOK + n)) * CDIM + h * 48;
#pragma unroll
        for (int d4 = 0; d4 < 12; d4++) {
            float s0 = 0.f, s1 = 0.f, s2 = 0.f, s3 = 0.f;
#pragma unroll
            for (int e = 0; e < 48; e++) {
                float ve = v[e];
                s0 += attn_s[d4 * 4 + 0][e] * ve;
                s1 += attn_s[d4 * 4 + 1][e] * ve;
                s2 += attn_s[d4 * 4 + 2][e] * ve;
                s3 += attn_s[d4 * 4 + 3][e] * ve;
            }
            float4 o; o.x = s0; o.y = s1; o.z = s2; o.w = s3;
            *(float4*)(g_att + ob + d4 * 4) = o;
        }
    }
}

// ---------------- final transpose token-major -> NCHW -----------------------
__global__ __launch_bounds__(256) void to_nchw_kernel(
    const float* __restrict__ src, float* __restrict__ out)
{
    __shared__ float tile[32][33];
    int b = blockIdx.z, c0 = blockIdx.y * 32, n0 = blockIdx.x * 32;
    int tx = threadIdx.x, ty = threadIdx.y;
#pragma unroll
    for (int r = 0; r < 4; r++)
        tile[ty + r * 8][tx] = src[((size_t)b * NTOK + n0 + ty + r * 8) * CDIM + c0 + tx];
    __syncthreads();
#pragma unroll
    for (int r = 0; r < 4; r++)
        out[((size_t)b * CDIM + c0 + ty + r * 8) * NTOK + n0 + tx] = tile[tx][ty + r * 8];
}

// ---------------------------------------------------------------------------
extern "C" void kernel_launch(void* const* d_in, const int* in_sizes, int n_in,
                              void* d_out, int out_size)
{
    const float* x       = (const float*)d_in[0];
    const float* dw_w0   = (const float*)d_in[1];
    const float* dw_b0   = (const float*)d_in[2];
    const float* dw_w1   = (const float*)d_in[3];
    const float* dw_b1   = (const float*)d_in[4];
    const float* ln1_g   = (const float*)d_in[5];
    const float* ln1_b   = (const float*)d_in[6];
    const float* qkv_w   = (const float*)d_in[7];
    const float* proj_w  = (const float*)d_in[8];
    const float* proj_b  = (const float*)d_in[9];
    const float* ln2_g   = (const float*)d_in[10];
    const float* ln2_b   = (const float*)d_in[11];
    const float* mlp1_dw = (const float*)d_in[12];
    const float* mlp1_uw = (const float*)d_in[13];
    const float* mlp1_ub = (const float*)d_in[14];
    const float* mlp2_dw = (const float*)d_in[15];
    const float* mlp2_uw = (const float*)d_in[16];
    const float* mlp2_ub = (const float*)d_in[17];
    float* out = (float*)d_out;

    float *big, *s1, *s2, *xf, *y, *att, *xf2, *t1, *t2;
    cudaGetSymbolAddress((void**)&big,  g_big);
    cudaGetSymbolAddress((void**)&s1,   g_s1);
    cudaGetSymbolAddress((void**)&s2,   g_s2);
    cudaGetSymbolAddress((void**)&xf,   g_xf);
    cudaGetSymbolAddress((void**)&y,    g_y);
    cudaGetSymbolAddress((void**)&att,  g_att);
    cudaGetSymbolAddress((void**)&xf2,  g_xf2);
    cudaGetSymbolAddress((void**)&t1,   g_t1);
    cudaGetSymbolAddress((void**)&t2,   g_t2);
    float* qkv  = big;   // [TOKS, 1152], lifetime ends after attn_kernel
    float* hbuf = big;   // [TOKS, 1536], lifetime starts after ln2

    int nconv = Bsz * SPLIT * NTOK;
    int cblk = (nconv + 255) / 256;

    // s1 = dwconv(s1 + s0), s2 = dwconv(s2 + s1_new)
    dwconv_kernel<<<cblk, 256>>>(x, (long)CDIM * NTOK,
                                 x + (size_t)SPLIT * NTOK, (long)CDIM * NTOK,
                                 dw_w0, dw_b0, s1);
    dwconv_kernel<<<cblk, 256>>>(s1, (long)SPLIT * NTOK,
                                 x + (size_t)2 * SPLIT * NTOK, (long)CDIM * NTOK,
                                 dw_w1, dw_b1, s2);

    // x_flat assembly [TOKS, 384]
    assemble_kernel<<<dim3(98, 12, Bsz), dim3(32, 8)>>>(x);

    // LN1 -> y
    ln_kernel<<<TOKS, 128>>>(xf, y, ln1_g, ln1_b);

    // qkv = y @ qkv_w  [TOKS, 1152]
    sgemm<<<dim3(1152 / BN, TOKS / BM), 256>>>(y, qkv_w, qkv, TOKS, 1152, 384,
                                               nullptr, nullptr, 0);

    // XCA attention -> g_att [TOKS, 384]
    attn_kernel<<<dim3(NHEAD, Bsz), 256>>>();

    // xf2 = xf + att @ proj_w + proj_b
    sgemm<<<dim3(384 / BN, TOKS / BM), 256>>>(att, proj_w, xf2, TOKS, 384, 384,
                                              proj_b, xf, 0);

    // LN2 -> y (reuse)
    ln_kernel<<<TOKS, 128>>>(xf2, y, ln2_g, ln2_b);

    // MLP low-rank: t1 = y @ mlp1_dw ; h = gelu(t1 @ mlp1_uw + b)
    sgemm<<<dim3(192 / BN, TOKS / BM), 256>>>(y, mlp1_dw, t1, TOKS, 192, 384,
                                              nullptr, nullptr, 0);
    sgemm<<<dim3(1536 / BN, TOKS / BM), 256>>>(t1, mlp1_uw, hbuf, TOKS, 1536, 192,
                                               mlp1_ub, nullptr, 1);
    // t2 = h @ mlp2_dw ; final = xf2 + t2 @ mlp2_uw + b  (into g_att, reuse)
    sgemm<<<dim3(192 / BN, TOKS / BM), 256>>>(hbuf, mlp2_dw, t2, TOKS, 192, 1536,
                                              nullptr, nullptr, 0);
    sgemm<<<dim3(384 / BN, TOKS / BM), 256>>>(t2, mlp2_uw, att, TOKS, 384, 192,
                                              mlp2_ub, xf2, 0);

    // transpose back to NCHW
    to_nchw_kernel<<<dim3(98, 12, Bsz), dim3(32, 8)>>>(att, out);

    (void)in_sizes; (void)n_in; (void)out_size;
}

// round 3
// speedup vs baseline: 1.4701x; 1.4701x over previous
#include <cuda_runtime.h>
#include <math.h>

#define Bsz   16
#define CDIM  384
#define HH    56
#define WW    56
#define NTOK  3136          // 56*56
#define TOKS  (Bsz*NTOK)    // 50176
#define NHEAD 8
#define HDm   48
#define SPLIT 128
#define HID   1536
#define RR    192

// ---------------- scratch (device globals: no allocations allowed) ----------
// g_big is time-shared: qkv [TOKS*1152] (dead after attention) then h [TOKS*1536]
__device__ float g_big[(size_t)TOKS*HID];
__device__ float g_s1 [(size_t)Bsz*SPLIT*NTOK];
__device__ float g_s2 [(size_t)Bsz*SPLIT*NTOK];
__device__ float g_xf [(size_t)TOKS*CDIM];
__device__ float g_y  [(size_t)TOKS*CDIM];     // ln1 out, reused for ln2 out (tf32-rounded)
__device__ float g_att[(size_t)TOKS*CDIM];     // attention out, reused for final
__device__ float g_xf2[(size_t)TOKS*CDIM];
__device__ float g_t1 [(size_t)TOKS*RR];
__device__ float g_t2 [(size_t)TOKS*RR];
// tf32 weights, packed: qkv | proj | m1d | m1u | m2d | m2u
#define WOFF_QKV 0
#define WOFF_PROJ 442368
#define WOFF_M1D 589824
#define WOFF_M1U 663552
#define WOFF_M2D 958464
#define WOFF_M2U 1253376
#define WTOTAL   1327104
__device__ unsigned g_wt[WTOTAL];

// ---------------- tf32 helpers ----------------------------------------------
__device__ __forceinline__ unsigned f2tf32(float f) {
    unsigned r;
    asm("cvt.rna.tf32.f32 %0, %1;" : "=r"(r) : "f"(f));
    return r;
}
__device__ __forceinline__ float tf32r(float f) {
    return __uint_as_float(f2tf32(f));
}
__device__ __forceinline__ void mma_tf32(
    float& d0, float& d1, float& d2, float& d3,
    unsigned a0, unsigned a1, unsigned a2, unsigned a3,
    unsigned b0, unsigned b1)
{
    asm volatile(
        "mma.sync.aligned.m16n8k8.row.col.f32.tf32.tf32.f32 "
        "{%0,%1,%2,%3}, {%4,%5,%6,%7}, {%8,%9}, {%0,%1,%2,%3};\n"
        : "+f"(d0), "+f"(d1), "+f"(d2), "+f"(d3)
        : "r"(a0), "r"(a1), "r"(a2), "r"(a3), "r"(b0), "r"(b1));
}

// ---------------- weight -> tf32 convert pass --------------------------------
__global__ __launch_bounds__(256) void wconv_kernel(
    const float* __restrict__ w0, const float* __restrict__ w1,
    const float* __restrict__ w2, const float* __restrict__ w3,
    const float* __restrict__ w4, const float* __restrict__ w5)
{
    int i = blockIdx.x * 256 + threadIdx.x;
    if (i >= WTOTAL) return;
    const float* s; int off;
    if      (i < WOFF_PROJ) { s = w0; off = WOFF_QKV; }
    else if (i < WOFF_M1D)  { s = w1; off = WOFF_PROJ; }
    else if (i < WOFF_M1U)  { s = w2; off = WOFF_M1D; }
    else if (i < WOFF_M2D)  { s = w3; off = WOFF_M1U; }
    else if (i < WOFF_M2U)  { s = w4; off = WOFF_M2D; }
    else                    { s = w5; off = WOFF_M2U; }
    g_wt[i] = f2tf32(s[i - off]);
}

// ---------------- depthwise 3x3 conv (correlation, SAME) --------------------
__global__ __launch_bounds__(256) void dwconv_kernel(
    const float* __restrict__ pA, long strideA,
    const float* __restrict__ pB, long strideB,
    const float* __restrict__ w, const float* __restrict__ bias,
    float* __restrict__ out)
{
    int idx = blockIdx.x * 256 + threadIdx.x;
    if (idx >= Bsz * SPLIT * NTOK) return;
    int n = idx % NTOK;
    int c = (idx / NTOK) % SPLIT;
    int b = idx / (NTOK * SPLIT);
    int hh = n / WW, ww = n % WW;
    const float* a  = pA + (size_t)b * strideA + (size_t)c * NTOK;
    const float* bb = pB + (size_t)b * strideB + (size_t)c * NTOK;
    float acc = bias[c];
#pragma unroll
    for (int i = 0; i < 3; i++) {
        int ih = hh + i - 1;
        if (ih < 0 || ih >= HH) continue;
#pragma unroll
        for (int j = 0; j < 3; j++) {
            int iw = ww + j - 1;
            if (iw < 0 || iw >= WW) continue;
            int off = ih * WW + iw;
            acc += w[c * 9 + i * 3 + j] * (a[off] + bb[off]);
        }
    }
    out[idx] = acc;
}

// ------------- assemble token-major x_flat from s0|s1|s2 (tiled transpose) --
__global__ __launch_bounds__(256) void assemble_kernel(const float* __restrict__ x)
{
    __shared__ float tile[32][33];
    int b = blockIdx.z, c0 = blockIdx.y * 32, n0 = blockIdx.x * 32;
    int tx = threadIdx.x, ty = threadIdx.y;
    const float* src;
    if (c0 < 128)      src = x    + ((size_t)b * CDIM  + c0)        * NTOK;
    else if (c0 < 256) src = g_s1 + ((size_t)b * SPLIT + (c0-128)) * NTOK;
    else               src = g_s2 + ((size_t)b * SPLIT + (c0-256)) * NTOK;
#pragma unroll
    for (int r = 0; r < 4; r++)
        tile[ty + r * 8][tx] = src[(size_t)(ty + r * 8) * NTOK + n0 + tx];
    __syncthreads();
#pragma unroll
    for (int r = 0; r < 4; r++)
        g_xf[((size_t)b * NTOK + n0 + ty + r * 8) * CDIM + c0 + tx] = tile[tx][ty + r * 8];
}

// ---------------- LayerNorm over C=384, tf32-rounded output -----------------
__global__ __launch_bounds__(128) void ln_kernel(
    const float* __restrict__ src, float* __restrict__ dst,
    const float* __restrict__ g, const float* __restrict__ bta)
{
    int tok = blockIdx.x;
    const float* r = src + (size_t)tok * CDIM;
    int tid = threadIdx.x;
    float v0 = r[tid], v1 = r[tid + 128], v2 = r[tid + 256];
    float s  = v0 + v1 + v2;
    float s2 = v0 * v0 + v1 * v1 + v2 * v2;
#pragma unroll
    for (int o = 16; o > 0; o >>= 1) {
        s  += __shfl_down_sync(0xFFFFFFFFu, s,  o);
        s2 += __shfl_down_sync(0xFFFFFFFFu, s2, o);
    }
    __shared__ float ss[4], ss2[4];
    int w = tid >> 5;
    if ((tid & 31) == 0) { ss[w] = s; ss2[w] = s2; }
    __syncthreads();
    if (tid == 0) {
        float a  = ss[0] + ss[1] + ss[2] + ss[3];
        float a2 = ss2[0] + ss2[1] + ss2[2] + ss2[3];
        float m  = a / CDIM;
        float var = a2 / CDIM - m * m;
        ss[0] = m; ss2[0] = rsqrtf(var + 1e-6f);
    }
    __syncthreads();
    float m = ss[0], rs = ss2[0];
    float* d = dst + (size_t)tok * CDIM;
    d[tid]       = tf32r((v0 - m) * rs * g[tid]       + bta[tid]);
    d[tid + 128] = tf32r((v1 - m) * rs * g[tid + 128] + bta[tid + 128]);
    d[tid + 256] = tf32r((v2 - m) * rs * g[tid + 256] + bta[tid + 256]);
}

// ---------------- tf32 tensor-core GEMM -------------------------------------
// C[M,N] = A[M,K] @ B[K,N]; A fp32 (already tf32-rounded), B pre-converted tf32.
// BM=128, BN=64, BK=32, 256 thr (8 warps), warp tile 32x32 via m16n8k8.
__global__ __launch_bounds__(256) void tgemm(
    const float* __restrict__ A, const unsigned* __restrict__ B, float* __restrict__ C,
    int M, int N, int K,
    const float* __restrict__ bias, const float* __restrict__ res,
    int do_gelu, int round_out)
{
    __shared__ unsigned As[32][129];
    __shared__ unsigned Bs[32][68];
    int tid = threadIdx.x, lane = tid & 31, wid = tid >> 5;
    int g = lane >> 2, t = lane & 3;
    int wm = wid & 3, wn = wid >> 2;
    const float*    Ab = A + (size_t)blockIdx.y * 128 * K;
    const unsigned* Bb = B + blockIdx.x * 64;

    float acc[2][4][4];
#pragma unroll
    for (int mf = 0; mf < 2; mf++)
#pragma unroll
        for (int nf = 0; nf < 4; nf++)
#pragma unroll
            for (int i = 0; i < 4; i++) acc[mf][nf][i] = 0.f;

    float4 ar[4]; uint4 br[2];
#pragma unroll
    for (int i = 0; i < 4; i++) {
        int f = tid + i * 256;
        ar[i] = *(const float4*)(Ab + (size_t)(f >> 3) * K + ((f & 7) << 2));
    }
#pragma unroll
    for (int i = 0; i < 2; i++) {
        int f = tid + i * 256;
        br[i] = *(const uint4*)(Bb + (size_t)(f >> 4) * N + ((f & 15) << 2));
    }

    for (int kk = 0; kk < K; kk += 32) {
#pragma unroll
        for (int i = 0; i < 4; i++) {
            int f = tid + i * 256;
            int m = f >> 3, k4 = (f & 7) << 2;
            As[k4 + 0][m] = __float_as_uint(ar[i].x);
            As[k4 + 1][m] = __float_as_uint(ar[i].y);
            As[k4 + 2][m] = __float_as_uint(ar[i].z);
            As[k4 + 3][m] = __float_as_uint(ar[i].w);
        }
#pragma unroll
        for (int i = 0; i < 2; i++) {
            int f = tid + i * 256;
            *(uint4*)&Bs[f >> 4][(f & 15) << 2] = br[i];
        }
        __syncthreads();
        if (kk + 32 < K) {
#pragma unroll
            for (int i = 0; i < 4; i++) {
                int f = tid + i * 256;
                ar[i] = *(const float4*)(Ab + (size_t)(f >> 3) * K + kk + 32 + ((f & 7) << 2));
            }
#pragma unroll
            for (int i = 0; i < 2; i++) {
                int f = tid + i * 256;
                br[i] = *(const uint4*)(Bb + (size_t)(kk + 32 + (f >> 4)) * N + ((f & 15) << 2));
            }
        }
#pragma unroll
        for (int ks = 0; ks < 4; ks++) {
            int kb = ks * 8;
            unsigned a[2][4], b[4][2];
#pragma unroll
            for (int mf = 0; mf < 2; mf++) {
                int m = wm * 32 + mf * 16;
                a[mf][0] = As[kb + t]    [m + g];
                a[mf][1] = As[kb + t]    [m + g + 8];
                a[mf][2] = As[kb + t + 4][m + g];
                a[mf][3] = As[kb + t + 4][m + g + 8];
            }
#pragma unroll
            for (int nf = 0; nf < 4; nf++) {
                int n = wn * 32 + nf * 8;
                b[nf][0] = Bs[kb + t]    [n + g];
                b[nf][1] = Bs[kb + t + 4][n + g];
            }
#pragma unroll
            for (int mf = 0; mf < 2; mf++)
#pragma unroll
                for (int nf = 0; nf < 4; nf++)
                    mma_tf32(acc[mf][nf][0], acc[mf][nf][1], acc[mf][nf][2], acc[mf][nf][3],
                             a[mf][0], a[mf][1], a[mf][2], a[mf][3],
                             b[nf][0], b[nf][1]);
        }
        __syncthreads();
    }

    // epilogue
#pragma unroll
    for (int mf = 0; mf < 2; mf++)
#pragma unroll
        for (int nf = 0; nf < 4; nf++) {
            int row = blockIdx.y * 128 + wm * 32 + mf * 16 + g;
            int col = blockIdx.x * 64 + wn * 32 + nf * 8 + 2 * t;
#pragma unroll
            for (int rr = 0; rr < 2; rr++) {
                int r2 = row + rr * 8;
                float v0 = acc[mf][nf][rr * 2 + 0];
                float v1 = acc[mf][nf][rr * 2 + 1];
                if (bias) { v0 += bias[col]; v1 += bias[col + 1]; }
                if (do_gelu) {
                    v0 = 0.5f * v0 * (1.f + erff(v0 * 0.70710678118f));
                    v1 = 0.5f * v1 * (1.f + erff(v1 * 0.70710678118f));
                }
                if (res) {
                    float2 rv = *(const float2*)(res + (size_t)r2 * N + col);
                    v0 += rv.x; v1 += rv.y;
                }
                if (round_out) { v0 = tf32r(v0); v1 = tf32r(v1); }
                float2 o; o.x = v0; o.y = v1;
                *(float2*)(C + (size_t)r2 * N + col) = o;
            }
        }
}

// ---------------- XCA attention: one block per (head, batch) ----------------
__global__ __launch_bounds__(256) void attn_kernel()
{
    int h = blockIdx.x, b = blockIdx.y;
    __shared__ float q_s[48][65];
    __shared__ float k_s[48][65];
    __shared__ float attn_s[48][48];
    __shared__ float qn[48], kn[48];
    int tid = threadIdx.x;
    int td = tid >> 4, te = tid & 15;

    float acc[3][3];
#pragma unroll
    for (int i = 0; i < 3; i++)
#pragma unroll
        for (int j = 0; j < 3; j++) acc[i][j] = 0.f;
    float qssl = 0.f, kssl = 0.f;

    for (int n0 = 0; n0 < NTOK; n0 += 64) {
        for (int i = tid; i < 48 * 64; i += 256) {
            int d = i % 48, nn = i / 48;
            size_t base = ((size_t)(b * NTOK + n0 + nn)) * 1152 + h * 48 + d;
            q_s[d][nn] = g_big[base];
            k_s[d][nn] = g_big[base + 384];
        }
        __syncthreads();
        if (tid < 48) {
            float t = 0.f;
#pragma unroll 8
            for (int nn = 0; nn < 64; nn++) { float v = q_s[tid][nn]; t += v * v; }
            qssl += t;
        } else if (tid >= 64 && tid < 112) {
            int d = tid - 64;
            float t = 0.f;
#pragma unroll 8
            for (int nn = 0; nn < 64; nn++) { float v = k_s[d][nn]; t += v * v; }
            kssl += t;
        }
#pragma unroll 4
        for (int nn = 0; nn < 64; nn++) {
            float qa0 = q_s[td * 3 + 0][nn], qa1 = q_s[td * 3 + 1][nn], qa2 = q_s[td * 3 + 2][nn];
            float kb0 = k_s[te * 3 + 0][nn], kb1 = k_s[te * 3 + 1][nn], kb2 = k_s[te * 3 + 2][nn];
            acc[0][0] += qa0 * kb0; acc[0][1] += qa0 * kb1; acc[0][2] += qa0 * kb2;
            acc[1][0] += qa1 * kb0; acc[1][1] += qa1 * kb1; acc[1][2] += qa1 * kb2;
            acc[2][0] += qa2 * kb0; acc[2][1] += qa2 * kb1; acc[2][2] += qa2 * kb2;
        }
        __syncthreads();
    }
    if (tid < 48)                 qn[tid]      = fmaxf(sqrtf(qssl), 1e-12f);
    if (tid >= 64 && tid < 112)   kn[tid - 64] = fmaxf(sqrtf(kssl), 1e-12f);
    __syncthreads();
#pragma unroll
    for (int i = 0; i < 3; i++)
#pragma unroll
        for (int j = 0; j < 3; j++)
            attn_s[td * 3 + i][te * 3 + j] = acc[i][j] / (qn[td * 3 + i] * kn[te * 3 + j]);
    __syncthreads();

    if (tid < 48) {
        float mx = -1e30f;
#pragma unroll 8
        for (int e = 0; e < 48; e++) mx = fmaxf(mx, attn_s[tid][e]);
        float sm = 0.f;
#pragma unroll 8
        for (int e = 0; e < 48; e++) {
            float t = expf(attn_s[tid][e] - mx);
            attn_s[tid][e] = t; sm += t;
        }
        float inv = 1.f / sm;
#pragma unroll 8
        for (int e = 0; e < 48; e++) attn_s[tid][e] *= inv;
    }
    __syncthreads();

    // Phase 2: y = attn @ V, output tf32-rounded (feeds proj GEMM as A)
    for (int n0 = 0; n0 < NTOK; n0 += 256) {
        int n = n0 + tid;
        if (n >= NTOK) break;
        size_t base = ((size_t)(b * NTOK + n)) * 1152 + 768 + h * 48;
        float v[48];
#pragma unroll
        for (int i = 0; i < 12; i++) {
            float4 t = *(const float4*)(g_big + base + i * 4);
            v[i * 4 + 0] = t.x; v[i * 4 + 1] = t.y; v[i * 4 + 2] = t.z; v[i * 4 + 3] = t.w;
        }
        size_t ob = ((size_t)(b * NTOK + n)) * CDIM + h * 48;
#pragma unroll
        for (int d4 = 0; d4 < 12; d4++) {
            float s0 = 0.f, s1 = 0.f, s2 = 0.f, s3 = 0.f;
#pragma unroll
            for (int e = 0; e < 48; e++) {
                float ve = v[e];
                s0 += attn_s[d4 * 4 + 0][e] * ve;
                s1 += attn_s[d4 * 4 + 1][e] * ve;
                s2 += attn_s[d4 * 4 + 2][e] * ve;
                s3 += attn_s[d4 * 4 + 3][e] * ve;
            }
            float4 o;
            o.x = tf32r(s0); o.y = tf32r(s1); o.z = tf32r(s2); o.w = tf32r(s3);
            *(float4*)(g_att + ob + d4 * 4) = o;
        }
    }
}

// ---------------- final transpose token-major -> NCHW -----------------------
__global__ __launch_bounds__(256) void to_nchw_kernel(
    const float* __restrict__ src, float* __restrict__ out)
{
    __shared__ float tile[32][33];
    int b = blockIdx.z, c0 = blockIdx.y * 32, n0 = blockIdx.x * 32;
    int tx = threadIdx.x, ty = threadIdx.y;
#pragma unroll
    for (int r = 0; r < 4; r++)
        tile[ty + r * 8][tx] = src[((size_t)b * NTOK + n0 + ty + r * 8) * CDIM + c0 + tx];
    __syncthreads();
#pragma unroll
    for (int r = 0; r < 4; r++)
        out[((size_t)b * CDIM + c0 + ty + r * 8) * NTOK + n0 + tx] = tile[tx][ty + r * 8];
}

// ---------------------------------------------------------------------------
extern "C" void kernel_launch(void* const* d_in, const int* in_sizes, int n_in,
                              void* d_out, int out_size)
{
    const float* x       = (const float*)d_in[0];
    const float* dw_w0   = (const float*)d_in[1];
    const float* dw_b0   = (const float*)d_in[2];
    const float* dw_w1   = (const float*)d_in[3];
    const float* dw_b1   = (const float*)d_in[4];
    const float* ln1_g   = (const float*)d_in[5];
    const float* ln1_b   = (const float*)d_in[6];
    const float* qkv_w   = (const float*)d_in[7];
    const float* proj_w  = (const float*)d_in[8];
    const float* proj_b  = (const float*)d_in[9];
    const float* ln2_g   = (const float*)d_in[10];
    const float* ln2_b   = (const float*)d_in[11];
    const float* mlp1_dw = (const float*)d_in[12];
    const float* mlp1_uw = (const float*)d_in[13];
    const float* mlp1_ub = (const float*)d_in[14];
    const float* mlp2_dw = (const float*)d_in[15];
    const float* mlp2_uw = (const float*)d_in[16];
    const float* mlp2_ub = (const float*)d_in[17];
    float* out = (float*)d_out;

    float *big, *s1, *s2, *xf, *y, *att, *xf2, *t1, *t2;
    unsigned* wt;
    cudaGetSymbolAddress((void**)&big,  g_big);
    cudaGetSymbolAddress((void**)&s1,   g_s1);
    cudaGetSymbolAddress((void**)&s2,   g_s2);
    cudaGetSymbolAddress((void**)&xf,   g_xf);
    cudaGetSymbolAddress((void**)&y,    g_y);
    cudaGetSymbolAddress((void**)&att,  g_att);
    cudaGetSymbolAddress((void**)&xf2,  g_xf2);
    cudaGetSymbolAddress((void**)&t1,   g_t1);
    cudaGetSymbolAddress((void**)&t2,   g_t2);
    cudaGetSymbolAddress((void**)&wt,   g_wt);
    float* qkv  = big;   // [TOKS, 1152], lifetime ends after attn_kernel
    float* hbuf = big;   // [TOKS, 1536], lifetime starts after ln2

    // weights -> tf32 (runs concurrently-safe: only writes g_wt)
    wconv_kernel<<<(WTOTAL + 255) / 256, 256>>>(qkv_w, proj_w, mlp1_dw, mlp1_uw,
                                                mlp2_dw, mlp2_uw);

    int nconv = Bsz * SPLIT * NTOK;
    int cblk = (nconv + 255) / 256;

    dwconv_kernel<<<cblk, 256>>>(x, (long)CDIM * NTOK,
                                 x + (size_t)SPLIT * NTOK, (long)CDIM * NTOK,
                                 dw_w0, dw_b0, s1);
    dwconv_kernel<<<cblk, 256>>>(s1, (long)SPLIT * NTOK,
                                 x + (size_t)2 * SPLIT * NTOK, (long)CDIM * NTOK,
                                 dw_w1, dw_b1, s2);

    assemble_kernel<<<dim3(98, 12, Bsz), dim3(32, 8)>>>(x);

    ln_kernel<<<TOKS, 128>>>(xf, y, ln1_g, ln1_b);

    // qkv = y @ qkv_w  [TOKS, 1152]
    tgemm<<<dim3(1152 / 64, TOKS / 128), 256>>>(y, wt + WOFF_QKV, qkv,
                                                TOKS, 1152, 384, nullptr, nullptr, 0, 0);

    attn_kernel<<<dim3(NHEAD, Bsz), 256>>>();

    // xf2 = xf + att @ proj_w + proj_b
    tgemm<<<dim3(384 / 64, TOKS / 128), 256>>>(att, wt + WOFF_PROJ, xf2,
                                               TOKS, 384, 384, proj_b, xf, 0, 0);

    ln_kernel<<<TOKS, 128>>>(xf2, y, ln2_g, ln2_b);

    // t1 = y @ mlp1_dw ; h = gelu(t1 @ mlp1_uw + b)
    tgemm<<<dim3(192 / 64, TOKS / 128), 256>>>(y, wt + WOFF_M1D, t1,
                                               TOKS, 192, 384, nullptr, nullptr, 0, 1);
    tgemm<<<dim3(1536 / 64, TOKS / 128), 256>>>(t1, wt + WOFF_M1U, hbuf,
                                                TOKS, 1536, 192, mlp1_ub, nullptr, 1, 1);
    // t2 = h @ mlp2_dw ; final = xf2 + t2 @ mlp2_uw + b  (into g_att, reuse)
    tgemm<<<dim3(192 / 64, TOKS / 128), 256>>>(hbuf, wt + WOFF_M2D, t2,
                                               TOKS, 192, 1536, nullptr, nullptr, 0, 1);
    tgemm<<<dim3(384 / 64, TOKS / 128), 256>>>(t2, wt + WOFF_M2U, att,
                                               TOKS, 384, 192, mlp2_ub, xf2, 0, 0);

    to_nchw_kernel<<<dim3(98, 12, Bsz), dim3(32, 8)>>>(att, out);

    (void)in_sizes; (void)n_in; (void)out_size;
}

// round 7
// speedup vs baseline: 2.6572x; 1.8075x over previous
#include <cuda_runtime.h>
#include <cuda_bf16.h>
#include <math.h>

#define Bsz   16
#define CDIM  384
#define HH    56
#define WW    56
#define NTOK  3136          // 56*56
#define TOKS  (Bsz*NTOK)    // 50176
#define NHEAD 8
#define SPLIT 128
#define HID   1536
#define RR    192

// ---------------- scratch (device globals; no allocations allowed) ----------
__device__ float g_big[(size_t)TOKS*1152];     // qkv fp32; later reused for final fp32 out
__device__ float g_s1 [(size_t)Bsz*SPLIT*NTOK];
__device__ float g_s2 [(size_t)Bsz*SPLIT*NTOK];
__device__ float g_xf [(size_t)TOKS*CDIM];
__device__ float g_xf2[(size_t)TOKS*CDIM];
__device__ __nv_bfloat16 g_y16 [(size_t)TOKS*CDIM];
__device__ __nv_bfloat16 g_att16[(size_t)TOKS*CDIM];
__device__ __nv_bfloat16 g_t116[(size_t)TOKS*RR];
__device__ __nv_bfloat16 g_t216[(size_t)TOKS*RR];
__device__ __nv_bfloat16 g_h16 [(size_t)TOKS*HID];
// transposed bf16 weights, [N, K] K-major rows
__device__ __nv_bfloat16 g_wq [1152*384];
__device__ __nv_bfloat16 g_wp [384*384];
__device__ __nv_bfloat16 g_w1d[192*384];
__device__ __nv_bfloat16 g_w1u[1536*192];
__device__ __nv_bfloat16 g_w2d[192*1536];
__device__ __nv_bfloat16 g_w2u[384*192];

// ---------------- helpers ----------------------------------------------------
__device__ __forceinline__ unsigned smem_u32(const void* p) {
    unsigned a;
    asm("{ .reg .u64 t; cvta.to.shared.u64 t, %1; cvt.u32.u64 %0, t; }"
        : "=r"(a) : "l"(p));
    return a;
}
__device__ __forceinline__ void cpasync16(unsigned dst, const void* src) {
    asm volatile("cp.async.cg.shared.global [%0], [%1], 16;" :: "r"(dst), "l"(src));
}
#define CP_COMMIT() asm volatile("cp.async.commit_group;" ::: "memory")
__device__ __forceinline__ void ldm_x4(unsigned& r0, unsigned& r1, unsigned& r2,
                                       unsigned& r3, unsigned addr) {
    asm volatile("ldmatrix.sync.aligned.m8n8.x4.shared.b16 {%0,%1,%2,%3}, [%4];"
                 : "=r"(r0), "=r"(r1), "=r"(r2), "=r"(r3) : "r"(addr));
}
__device__ __forceinline__ void mma_bf16(float* d, const unsigned* a,
                                         unsigned b0, unsigned b1) {
    asm volatile(
        "mma.sync.aligned.m16n8k16.row.col.f32.bf16.bf16.f32 "
        "{%0,%1,%2,%3}, {%4,%5,%6,%7}, {%8,%9}, {%0,%1,%2,%3};\n"
        : "+f"(d[0]), "+f"(d[1]), "+f"(d[2]), "+f"(d[3])
        : "r"(a[0]), "r"(a[1]), "r"(a[2]), "r"(a[3]), "r"(b0), "r"(b1));
}

// ---------------- bf16 tensor-core GEMM: C[M,N] = A[M,K] @ Wt[N,K]^T ---------
// 128x64 block tile, 8 warps (4x2), warp tile 32x32, K-chunk 32, cp.async 2-stage.
#define ASTR 40   // padded row stride (bf16): 32 data + 8 pad -> conflict-free ldmatrix
__global__ __launch_bounds__(256) void bgemm(
    const __nv_bfloat16* __restrict__ A, const __nv_bfloat16* __restrict__ Bw,
    float* __restrict__ Cf, __nv_bfloat16* __restrict__ Cb,
    int M, int N, int K,
    const float* __restrict__ bias, const float* __restrict__ res, int do_gelu)
{
    __shared__ __align__(16) __nv_bfloat16 As[2][128][ASTR];
    __shared__ __align__(16) __nv_bfloat16 Bs[2][64][ASTR];
    int tid = threadIdx.x, lane = tid & 31, wid = tid >> 5;
    int wm = wid & 3, wn = wid >> 2;
    const __nv_bfloat16* Ab = A  + (size_t)blockIdx.y * 128 * K;
    const __nv_bfloat16* Bb = Bw + (size_t)blockIdx.x * 64 * K;

    float acc[2][4][4];
#pragma unroll
    for (int mf = 0; mf < 2; mf++)
#pragma unroll
        for (int nf = 0; nf < 4; nf++)
#pragma unroll
            for (int i = 0; i < 4; i++) acc[mf][nf][i] = 0.f;

    int nk = K >> 5;
    int lrowA = tid >> 2, lseg = tid & 3;   // A: 2 iters of 256; B: 1 iter

    // prologue: load chunk 0 into buf 0
    {
#pragma unroll
        for (int i = 0; i < 2; i++) {
            int row = lrowA + i * 64;
            cpasync16(smem_u32(&As[0][row][lseg * 8]),
                      Ab + (size_t)row * K + lseg * 8);
        }
        int rowb = tid >> 2;
        if (rowb < 64)
            cpasync16(smem_u32(&Bs[0][rowb][lseg * 8]),
                      Bb + (size_t)rowb * K + lseg * 8);
        CP_COMMIT();
    }

    for (int kc = 0; kc < nk; kc++) {
        int buf = kc & 1;
        if (kc + 1 < nk) {
            int nbuf = buf ^ 1;
            long kb = (long)(kc + 1) * 32;
#pragma unroll
            for (int i = 0; i < 2; i++) {
                int row = lrowA + i * 64;
                cpasync16(smem_u32(&As[nbuf][row][lseg * 8]),
                          Ab + (size_t)row * K + kb + lseg * 8);
            }
            int rowb = tid >> 2;
            if (rowb < 64)
                cpasync16(smem_u32(&Bs[nbuf][rowb][lseg * 8]),
                          Bb + (size_t)rowb * K + kb + lseg * 8);
            CP_COMMIT();
            asm volatile("cp.async.wait_group 1;" ::: "memory");
        } else {
            asm volatile("cp.async.wait_group 0;" ::: "memory");
        }
        __syncthreads();

#pragma unroll
        for (int ks = 0; ks < 2; ks++) {
            unsigned a[2][4], bb[4][2];
#pragma unroll
            for (int mf = 0; mf < 2; mf++) {
                int r = wm * 32 + mf * 16 + (lane & 15);
                int c = ks * 16 + (lane >> 4) * 8;
                ldm_x4(a[mf][0], a[mf][1], a[mf][2], a[mf][3],
                       smem_u32(&As[buf][r][c]));
            }
#pragma unroll
            for (int nh = 0; nh < 2; nh++) {
                int r = wn * 32 + nh * 16 + (lane >> 4) * 8 + (lane & 7);
                int c = ks * 16 + ((lane >> 3) & 1) * 8;
                unsigned r0, r1, r2, r3;
                ldm_x4(r0, r1, r2, r3, smem_u32(&Bs[buf][r][c]));
                bb[nh * 2][0] = r0; bb[nh * 2][1] = r1;
                bb[nh * 2 + 1][0] = r2; bb[nh * 2 + 1][1] = r3;
            }
#pragma unroll
            for (int mf = 0; mf < 2; mf++)
#pragma unroll
                for (int nf = 0; nf < 4; nf++)
                    mma_bf16(acc[mf][nf], a[mf], bb[nf][0], bb[nf][1]);
        }
        __syncthreads();
    }

    // epilogue
    int g = lane >> 2, t = lane & 3;
#pragma unroll
    for (int mf = 0; mf < 2; mf++)
#pragma unroll
        for (int nf = 0; nf < 4; nf++) {
            int col = blockIdx.x * 64 + wn * 32 + nf * 8 + 2 * t;
#pragma unroll
            for (int rr = 0; rr < 2; rr++) {
                int row = blockIdx.y * 128 + wm * 32 + mf * 16 + g + rr * 8;
                float v0 = acc[mf][nf][rr * 2 + 0];
                float v1 = acc[mf][nf][rr * 2 + 1];
                if (bias) { v0 += __ldg(&bias[col]); v1 += __ldg(&bias[col + 1]); }
                if (do_gelu) {
                    v0 = 0.5f * v0 * (1.f + erff(v0 * 0.70710678118f));
                    v1 = 0.5f * v1 * (1.f + erff(v1 * 0.70710678118f));
                }
                if (res) {
                    float2 rv = *(const float2*)(res + (size_t)row * N + col);
                    v0 += rv.x; v1 += rv.y;
                }
                if (Cf) {
                    float2 o; o.x = v0; o.y = v1;
                    *(float2*)(Cf + (size_t)row * N + col) = o;
                } else {
                    __nv_bfloat162 b2 = __floats2bfloat162_rn(v0, v1);
                    *(__nv_bfloat162*)(Cb + (size_t)row * N + col) = b2;
                }
            }
        }
}

// ---------------- weight transpose fp32[K,N] -> bf16[N,K] --------------------
__global__ __launch_bounds__(256) void wtrans_kernel(
    const float* __restrict__ W, __nv_bfloat16* __restrict__ Wt, int K, int N)
{
    int i = blockIdx.x * 256 + threadIdx.x;
    if (i >= K * N) return;
    int n = i / K, k = i - n * K;
    Wt[i] = __float2bfloat16(W[(size_t)k * N + n]);
}

// ---------------- depthwise 3x3 conv (correlation, SAME) --------------------
__global__ __launch_bounds__(256) void dwconv_kernel(
    const float* __restrict__ pA, long strideA,
    const float* __restrict__ pB, long strideB,
    const float* __restrict__ w, const float* __restrict__ bias,
    float* __restrict__ out)
{
    int idx = blockIdx.x * 256 + threadIdx.x;
    if (idx >= Bsz * SPLIT * NTOK) return;
    int n = idx % NTOK;
    int c = (idx / NTOK) % SPLIT;
    int b = idx / (NTOK * SPLIT);
    int hh = n / WW, ww = n % WW;
    const float* a  = pA + (size_t)b * strideA + (size_t)c * NTOK;
    const float* bb = pB + (size_t)b * strideB + (size_t)c * NTOK;
    float acc = bias[c];
#pragma unroll
    for (int i = 0; i < 3; i++) {
        int ih = hh + i - 1;
        if (ih < 0 || ih >= HH) continue;
#pragma unroll
        for (int j = 0; j < 3; j++) {
            int iw = ww + j - 1;
            if (iw < 0 || iw >= WW) continue;
            int off = ih * WW + iw;
            acc += w[c * 9 + i * 3 + j] * (a[off] + bb[off]);
        }
    }
    out[idx] = acc;
}

// ------------- assemble token-major x_flat from s0|s1|s2 (tiled transpose) --
__global__ __launch_bounds__(256) void assemble_kernel(const float* __restrict__ x)
{
    __shared__ float tile[32][33];
    int b = blockIdx.z, c0 = blockIdx.y * 32, n0 = blockIdx.x * 32;
    int tx = threadIdx.x, ty = threadIdx.y;
    const float* src;
    if (c0 < 128)      src = x    + ((size_t)b * CDIM  + c0)        * NTOK;
    else if (c0 < 256) src = g_s1 + ((size_t)b * SPLIT + (c0-128)) * NTOK;
    else               src = g_s2 + ((size_t)b * SPLIT + (c0-256)) * NTOK;
#pragma unroll
    for (int r = 0; r < 4; r++)
        tile[ty + r * 8][tx] = src[(size_t)(ty + r * 8) * NTOK + n0 + tx];
    __syncthreads();
#pragma unroll
    for (int r = 0; r < 4; r++)
        g_xf[((size_t)b * NTOK + n0 + ty + r * 8) * CDIM + c0 + tx] = tile[tx][ty + r * 8];
}

// ---------------- LayerNorm over C=384, bf16 output -------------------------
__global__ __launch_bounds__(128) void ln_kernel(
    const float* __restrict__ src, __nv_bfloat16* __restrict__ dst,
    const float* __restrict__ g, const float* __restrict__ bta)
{
    int tok = blockIdx.x;
    const float* r = src + (size_t)tok * CDIM;
    int tid = threadIdx.x;
    float v0 = r[tid], v1 = r[tid + 128], v2 = r[tid + 256];
    float s  = v0 + v1 + v2;
    float s2 = v0 * v0 + v1 * v1 + v2 * v2;
#pragma unroll
    for (int o = 16; o > 0; o >>= 1) {
        s  += __shfl_down_sync(0xFFFFFFFFu, s,  o);
        s2 += __shfl_down_sync(0xFFFFFFFFu, s2, o);
    }
    __shared__ float ss[4], ss2[4];
    int w = tid >> 5;
    if ((tid & 31) == 0) { ss[w] = s; ss2[w] = s2; }
    __syncthreads();
    if (tid == 0) {
        float a  = ss[0] + ss[1] + ss[2] + ss[3];
        float a2 = ss2[0] + ss2[1] + ss2[2] + ss2[3];
        float m  = a / CDIM;
        float var = a2 / CDIM - m * m;
        ss[0] = m; ss2[0] = rsqrtf(var + 1e-6f);
    }
    __syncthreads();
    float m = ss[0], rs = ss2[0];
    __nv_bfloat16* d = dst + (size_t)tok * CDIM;
    d[tid]       = __float2bfloat16((v0 - m) * rs * g[tid]       + bta[tid]);
    d[tid + 128] = __float2bfloat16((v1 - m) * rs * g[tid + 128] + bta[tid + 128]);
    d[tid + 256] = __float2bfloat16((v2 - m) * rs * g[tid + 256] + bta[tid + 256]);
}

// ---------------- XCA attention: one block per (head, batch) ----------------
__global__ __launch_bounds__(256) void attn_kernel()
{
    int h = blockIdx.x, b = blockIdx.y;
    __shared__ float q_s[48][65];
    __shared__ float k_s[48][65];
    __shared__ float attn_s[48][48];
    __shared__ float qn[48], kn[48];
    int tid = threadIdx.x;
    int td = tid >> 4, te = tid & 15;

    float acc[3][3];
#pragma unroll
    for (int i = 0; i < 3; i++)
#pragma unroll
        for (int j = 0; j < 3; j++) acc[i][j] = 0.f;
    float qssl = 0.f, kssl = 0.f;

    for (int n0 = 0; n0 < NTOK; n0 += 64) {
        for (int i = tid; i < 48 * 64; i += 256) {
            int d = i % 48, nn = i / 48;
            size_t base = ((size_t)(b * NTOK + n0 + nn)) * 1152 + h * 48 + d;
            q_s[d][nn] = g_big[base];
            k_s[d][nn] = g_big[base + 384];
        }
        __syncthreads();
        if (tid < 48) {
            float t = 0.f;
#pragma unroll 8
            for (int nn = 0; nn < 64; nn++) { float vv = q_s[tid][nn]; t += vv * vv; }
            qssl += t;
        } else if (tid >= 64 && tid < 112) {
            int d = tid - 64;
            float t = 0.f;
#pragma unroll 8
            for (int nn = 0; nn < 64; nn++) { float vv = k_s[d][nn]; t += vv * vv; }
            kssl += t;
        }
#pragma unroll 4
        for (int nn = 0; nn < 64; nn++) {
            float qa0 = q_s[td * 3 + 0][nn], qa1 = q_s[td * 3 + 1][nn], qa2 = q_s[td * 3 + 2][nn];
            float kb0 = k_s[te * 3 + 0][nn], kb1 = k_s[te * 3 + 1][nn], kb2 = k_s[te * 3 + 2][nn];
            acc[0][0] += qa0 * kb0; acc[0][1] += qa0 * kb1; acc[0][2] += qa0 * kb2;
            acc[1][0] += qa1 * kb0; acc[1][1] += qa1 * kb1; acc[1][2] += qa1 * kb2;
            acc[2][0] += qa2 * kb0; acc[2][1] += qa2 * kb1; acc[2][2] += qa2 * kb2;
        }
        __syncthreads();
    }
    if (tid < 48)                 qn[tid]      = fmaxf(sqrtf(qssl), 1e-12f);
    if (tid >= 64 && tid < 112)   kn[tid - 64] = fmaxf(sqrtf(kssl), 1e-12f);
    __syncthreads();
#pragma unroll
    for (int i = 0; i < 3; i++)
#pragma unroll
        for (int j = 0; j < 3; j++)
            attn_s[td * 3 + i][te * 3 + j] = acc[i][j] / (qn[td * 3 + i] * kn[te * 3 + j]);
    __syncthreads();

    if (tid < 48) {
        float mx = -1e30f;
#pragma unroll 8
        for (int e = 0; e < 48; e++) mx = fmaxf(mx, attn_s[tid][e]);
        float sm = 0.f;
#pragma unroll 8
        for (int e = 0; e < 48; e++) {
            float t = expf(attn_s[tid][e] - mx);
            attn_s[tid][e] = t; sm += t;
        }
        float inv = 1.f / sm;
#pragma unroll 8
        for (int e = 0; e < 48; e++) attn_s[tid][e] *= inv;
    }
    __syncthreads();

    // Phase 2: y = attn @ V, bf16 output (feeds proj GEMM as A operand)
    for (int n0 = 0; n0 < NTOK; n0 += 256) {
        int n = n0 + tid;
        if (n >= NTOK) break;
        size_t base = ((size_t)(b * NTOK + n)) * 1152 + 768 + h * 48;
        float v[48];
#pragma unroll
        for (int i = 0; i < 12; i++) {
            float4 t = *(const float4*)(g_big + base + i * 4);
            v[i * 4 + 0] = t.x; v[i * 4 + 1] = t.y; v[i * 4 + 2] = t.z; v[i * 4 + 3] = t.w;
        }
        __nv_bfloat16* ob = g_att16 + ((size_t)(b * NTOK + n)) * CDIM + h * 48;
#pragma unroll
        for (int d4 = 0; d4 < 12; d4++) {
            float s0 = 0.f, s1 = 0.f, s2 = 0.f, s3 = 0.f;
#pragma unroll
            for (int e = 0; e < 48; e++) {
                float ve = v[e];
                s0 += attn_s[d4 * 4 + 0][e] * ve;
                s1 += attn_s[d4 * 4 + 1][e] * ve;
                s2 += attn_s[d4 * 4 + 2][e] * ve;
                s3 += attn_s[d4 * 4 + 3][e] * ve;
            }
            __nv_bfloat162 p0 = __floats2bfloat162_rn(s0, s1);
            __nv_bfloat162 p1 = __floats2bfloat162_rn(s2, s3);
            uint2 o; o.x = *(unsigned*)&p0; o.y = *(unsigned*)&p1;
            *(uint2*)(ob + d4 * 4) = o;
        }
    }
}

// ---------------- final transpose token-major -> NCHW -----------------------
__global__ __launch_bounds__(256) void to_nchw_kernel(
    const float* __restrict__ src, float* __restrict__ out)
{
    __shared__ float tile[32][33];
    int b = blockIdx.z, c0 = blockIdx.y * 32, n0 = blockIdx.x * 32;
    int tx = threadIdx.x, ty = threadIdx.y;
#pragma unroll
    for (int r = 0; r < 4; r++)
        tile[ty + r * 8][tx] = src[((size_t)b * NTOK + n0 + ty + r * 8) * CDIM + c0 + tx];
    __syncthreads();
#pragma unroll
    for (int r = 0; r < 4; r++)
        out[((size_t)b * CDIM + c0 + ty + r * 8) * NTOK + n0 + tx] = tile[tx][ty + r * 8];
}

// ---------------------------------------------------------------------------
extern "C" void kernel_launch(void* const* d_in, const int* in_sizes, int n_in,
                              void* d_out, int out_size)
{
    const float* x       = (const float*)d_in[0];
    const float* dw_w0   = (const float*)d_in[1];
    const float* dw_b0   = (const float*)d_in[2];
    const float* dw_w1   = (const float*)d_in[3];
    const float* dw_b1   = (const float*)d_in[4];
    const float* ln1_g   = (const float*)d_in[5];
    const float* ln1_b   = (const float*)d_in[6];
    const float* qkv_w   = (const float*)d_in[7];
    const float* proj_w  = (const float*)d_in[8];
    const float* proj_b  = (const float*)d_in[9];
    const float* ln2_g   = (const float*)d_in[10];
    const float* ln2_b   = (const float*)d_in[11];
    const float* mlp1_dw = (const float*)d_in[12];
    const float* mlp1_uw = (const float*)d_in[13];
    const float* mlp1_ub = (const float*)d_in[14];
    const float* mlp2_dw = (const float*)d_in[15];
    const float* mlp2_uw = (const float*)d_in[16];
    const float* mlp2_ub = (const float*)d_in[17];
    float* out = (float*)d_out;

    float *big, *s1, *s2, *xf, *xf2;
    __nv_bfloat16 *y16, *att16, *t116, *t216, *h16;
    __nv_bfloat16 *wq, *wp, *w1d, *w1u, *w2d, *w2u;
    cudaGetSymbolAddress((void**)&big,  g_big);
    cudaGetSymbolAddress((void**)&s1,   g_s1);
    cudaGetSymbolAddress((void**)&s2,   g_s2);
    cudaGetSymbolAddress((void**)&xf,   g_xf);
    cudaGetSymbolAddress((void**)&xf2,  g_xf2);
    cudaGetSymbolAddress((void**)&y16,  g_y16);
    cudaGetSymbolAddress((void**)&att16,g_att16);
    cudaGetSymbolAddress((void**)&t116, g_t116);
    cudaGetSymbolAddress((void**)&t216, g_t216);
    cudaGetSymbolAddress((void**)&h16,  g_h16);
    cudaGetSymbolAddress((void**)&wq,   g_wq);
    cudaGetSymbolAddress((void**)&wp,   g_wp);
    cudaGetSymbolAddress((void**)&w1d,  g_w1d);
    cudaGetSymbolAddress((void**)&w1u,  g_w1u);
    cudaGetSymbolAddress((void**)&w2d,  g_w2d);
    cudaGetSymbolAddress((void**)&w2u,  g_w2u);

    // weight transposes (fp32 [K,N] -> bf16 [N,K])
    wtrans_kernel<<<(384*1152 + 255)/256, 256>>>(qkv_w,  wq,  384, 1152);
    wtrans_kernel<<<(384*384  + 255)/256, 256>>>(proj_w, wp,  384, 384);
    wtrans_kernel<<<(384*192  + 255)/256, 256>>>(mlp1_dw,w1d, 384, 192);
    wtrans_kernel<<<(192*1536 + 255)/256, 256>>>(mlp1_uw,w1u, 192, 1536);
    wtrans_kernel<<<(1536*192 + 255)/256, 256>>>(mlp2_dw,w2d, 1536, 192);
    wtrans_kernel<<<(192*384  + 255)/256, 256>>>(mlp2_uw,w2u, 192, 384);

    int nconv = Bsz * SPLIT * NTOK;
    int cblk = (nconv + 255) / 256;

    dwconv_kernel<<<cblk, 256>>>(x, (long)CDIM * NTOK,
                                 x + (size_t)SPLIT * NTOK, (long)CDIM * NTOK,
                                 dw_w0, dw_b0, s1);
    dwconv_kernel<<<cblk, 256>>>(s1, (long)SPLIT * NTOK,
                                 x + (size_t)2 * SPLIT * NTOK, (long)CDIM * NTOK,
                                 dw_w1, dw_b1, s2);

    assemble_kernel<<<dim3(98, 12, Bsz), dim3(32, 8)>>>(x);

    ln_kernel<<<TOKS, 128>>>(xf, y16, ln1_g, ln1_b);

    // qkv = y @ qkv_w  [TOKS, 1152]  (fp32 out into g_big)
    bgemm<<<dim3(1152/64, TOKS/128), 256>>>(y16, wq, big, nullptr,
                                            TOKS, 1152, 384, nullptr, nullptr, 0);

    attn_kernel<<<dim3(NHEAD, Bsz), 256>>>();

    // xf2 = xf + att @ proj_w + proj_b   (fp32 out)
    bgemm<<<dim3(384/64, TOKS/128), 256>>>(att16, wp, xf2, nullptr,
                                           TOKS, 384, 384, proj_b, xf, 0);

    ln_kernel<<<TOKS, 128>>>(xf2, y16, ln2_g, ln2_b);

    // t1 = y @ mlp1_dw (bf16 out); h = gelu(t1 @ mlp1_uw + b) (bf16 out)
    bgemm<<<dim3(192/64, TOKS/128), 256>>>(y16, w1d, nullptr, t116,
                                           TOKS, 192, 384, nullptr, nullptr, 0);
    bgemm<<<dim3(1536/64, TOKS/128), 256>>>(t116, w1u, nullptr, h16,
                                            TOKS, 1536, 192, mlp1_ub, nullptr, 1);
    // t2 = h @ mlp2_dw (bf16); final = xf2 + t2 @ mlp2_uw + b (fp32, into g_big)
    bgemm<<<dim3(192/64, TOKS/128), 256>>>(h16, w2d, nullptr, t216,
                                           TOKS, 192, 1536, nullptr, nullptr, 0);
    bgemm<<<dim3(384/64, TOKS/128), 256>>>(t216, w2u, big, nullptr,
                                           TOKS, 384, 192, mlp2_ub, xf2, 0);

    to_nchw_kernel<<<dim3(98, 12, Bsz), dim3(32, 8)>>>(big, out);

    (void)in_sizes; (void)n_in; (void)out_size;
}

// round 8
// speedup vs baseline: 2.8800x; 1.0839x over previous
#include <cuda_runtime.h>
#include <cuda_bf16.h>
#include <math.h>

#define Bsz   16
#define CDIM  384
#define HH    56
#define WW    56
#define NTOK  3136          // 56*56
#define TOKS  (Bsz*NTOK)    // 50176
#define NHEAD 8
#define SPLIT 128
#define HID   1536
#define RR    192

// ---------------- scratch (device globals; no allocations allowed) ----------
__device__ float g_big[(size_t)TOKS*1152];     // qkv fp32; later reused for final fp32 out
__device__ float g_s1 [(size_t)Bsz*SPLIT*NTOK];
__device__ float g_s2 [(size_t)Bsz*SPLIT*NTOK];
__device__ float g_xf [(size_t)TOKS*CDIM];
__device__ float g_xf2[(size_t)TOKS*CDIM];
__device__ __nv_bfloat16 g_y16 [(size_t)TOKS*CDIM];
__device__ __nv_bfloat16 g_att16[(size_t)TOKS*CDIM];
__device__ __nv_bfloat16 g_t116[(size_t)TOKS*RR];
__device__ __nv_bfloat16 g_t216[(size_t)TOKS*RR];
__device__ __nv_bfloat16 g_h16 [(size_t)TOKS*HID];
// transposed bf16 weights, [N, K] K-major rows
__device__ __nv_bfloat16 g_wq [1152*384];
__device__ __nv_bfloat16 g_wp [384*384];
__device__ __nv_bfloat16 g_w1d[192*384];
__device__ __nv_bfloat16 g_w1u[1536*192];
__device__ __nv_bfloat16 g_w2d[192*1536];
__device__ __nv_bfloat16 g_w2u[384*192];

// ---------------- helpers ----------------------------------------------------
__device__ __forceinline__ unsigned smem_u32(const void* p) {
    unsigned a;
    asm("{ .reg .u64 t; cvta.to.shared.u64 t, %1; cvt.u32.u64 %0, t; }"
        : "=r"(a) : "l"(p));
    return a;
}
__device__ __forceinline__ void cpasync16(unsigned dst, const void* src) {
    asm volatile("cp.async.cg.shared.global [%0], [%1], 16;" :: "r"(dst), "l"(src));
}
#define CP_COMMIT() asm volatile("cp.async.commit_group;" ::: "memory")
__device__ __forceinline__ void ldm_x4(unsigned& r0, unsigned& r1, unsigned& r2,
                                       unsigned& r3, unsigned addr) {
    asm volatile("ldmatrix.sync.aligned.m8n8.x4.shared.b16 {%0,%1,%2,%3}, [%4];"
                 : "=r"(r0), "=r"(r1), "=r"(r2), "=r"(r3) : "r"(addr));
}
__device__ __forceinline__ void mma_bf16(float* d, const unsigned* a,
                                         unsigned b0, unsigned b1) {
    asm volatile(
        "mma.sync.aligned.m16n8k16.row.col.f32.bf16.bf16.f32 "
        "{%0,%1,%2,%3}, {%4,%5,%6,%7}, {%8,%9}, {%0,%1,%2,%3};\n"
        : "+f"(d[0]), "+f"(d[1]), "+f"(d[2]), "+f"(d[3])
        : "r"(a[0]), "r"(a[1]), "r"(a[2]), "r"(a[3]), "r"(b0), "r"(b1));
}

#define ASTR 40   // padded row stride (bf16): 32 data + 8 pad -> conflict-free ldmatrix

// ============ bf16 GEMM, 128x128 tile (N % 128 == 0) =========================
// 8 warps as 2x4: warp tile 64x32. K-chunk 32, cp.async 2-stage, 40KB smem.
__global__ __launch_bounds__(256) void bgemm128(
    const __nv_bfloat16* __restrict__ A, const __nv_bfloat16* __restrict__ Bw,
    float* __restrict__ Cf, __nv_bfloat16* __restrict__ Cb,
    int M, int N, int K,
    const float* __restrict__ bias, const float* __restrict__ res, int do_gelu)
{
    __shared__ __align__(16) __nv_bfloat16 As[2][128][ASTR];
    __shared__ __align__(16) __nv_bfloat16 Bs[2][128][ASTR];
    int tid = threadIdx.x, lane = tid & 31, wid = tid >> 5;
    int wm = wid & 1, wn = wid >> 1;          // 2 x 4 warp grid
    const __nv_bfloat16* Ab = A  + (size_t)blockIdx.y * 128 * K;
    const __nv_bfloat16* Bb = Bw + (size_t)blockIdx.x * 128 * K;

    float acc[4][4][4];
#pragma unroll
    for (int mf = 0; mf < 4; mf++)
#pragma unroll
        for (int nf = 0; nf < 4; nf++)
#pragma unroll
            for (int i = 0; i < 4; i++) acc[mf][nf][i] = 0.f;

    int nk = K >> 5;
    int lrow = tid >> 2, lseg = tid & 3;

    // prologue
#pragma unroll
    for (int i = 0; i < 2; i++) {
        int row = lrow + i * 64;
        cpasync16(smem_u32(&As[0][row][lseg * 8]), Ab + (size_t)row * K + lseg * 8);
        cpasync16(smem_u32(&Bs[0][row][lseg * 8]), Bb + (size_t)row * K + lseg * 8);
    }
    CP_COMMIT();

    for (int kc = 0; kc < nk; kc++) {
        int buf = kc & 1;
        if (kc + 1 < nk) {
            int nbuf = buf ^ 1;
            long kb = (long)(kc + 1) * 32;
#pragma unroll
            for (int i = 0; i < 2; i++) {
                int row = lrow + i * 64;
                cpasync16(smem_u32(&As[nbuf][row][lseg * 8]),
                          Ab + (size_t)row * K + kb + lseg * 8);
                cpasync16(smem_u32(&Bs[nbuf][row][lseg * 8]),
                          Bb + (size_t)row * K + kb + lseg * 8);
            }
            CP_COMMIT();
            asm volatile("cp.async.wait_group 1;" ::: "memory");
        } else {
            asm volatile("cp.async.wait_group 0;" ::: "memory");
        }
        __syncthreads();

#pragma unroll
        for (int ks = 0; ks < 2; ks++) {
            unsigned a[4][4], bb[4][2];
#pragma unroll
            for (int mf = 0; mf < 4; mf++) {
                int r = wm * 64 + mf * 16 + (lane & 15);
                int c = ks * 16 + (lane >> 4) * 8;
                ldm_x4(a[mf][0], a[mf][1], a[mf][2], a[mf][3],
                       smem_u32(&As[buf][r][c]));
            }
#pragma unroll
            for (int nh = 0; nh < 2; nh++) {
                int r = wn * 32 + nh * 16 + (lane >> 4) * 8 + (lane & 7);
                int c = ks * 16 + ((lane >> 3) & 1) * 8;
                unsigned r0, r1, r2, r3;
                ldm_x4(r0, r1, r2, r3, smem_u32(&Bs[buf][r][c]));
                bb[nh * 2][0] = r0; bb[nh * 2][1] = r1;
                bb[nh * 2 + 1][0] = r2; bb[nh * 2 + 1][1] = r3;
            }
#pragma unroll
            for (int mf = 0; mf < 4; mf++)
#pragma unroll
                for (int nf = 0; nf < 4; nf++)
                    mma_bf16(acc[mf][nf], a[mf], bb[nf][0], bb[nf][1]);
        }
        __syncthreads();
    }

    // epilogue
    int g = lane >> 2, t = lane & 3;
#pragma unroll
    for (int mf = 0; mf < 4; mf++)
#pragma unroll
        for (int nf = 0; nf < 4; nf++) {
            int col = blockIdx.x * 128 + wn * 32 + nf * 8 + 2 * t;
#pragma unroll
            for (int rr = 0; rr < 2; rr++) {
                int row = blockIdx.y * 128 + wm * 64 + mf * 16 + g + rr * 8;
                float v0 = acc[mf][nf][rr * 2 + 0];
                float v1 = acc[mf][nf][rr * 2 + 1];
                if (bias) { v0 += __ldg(&bias[col]); v1 += __ldg(&bias[col + 1]); }
                if (do_gelu) {
                    v0 = 0.5f * v0 * (1.f + erff(v0 * 0.70710678118f));
                    v1 = 0.5f * v1 * (1.f + erff(v1 * 0.70710678118f));
                }
                if (res) {
                    float2 rv = *(const float2*)(res + (size_t)row * N + col);
                    v0 += rv.x; v1 += rv.y;
                }
                if (Cf) {
                    float2 o; o.x = v0; o.y = v1;
                    *(float2*)(Cf + (size_t)row * N + col) = o;
                } else {
                    __nv_bfloat162 b2 = __floats2bfloat162_rn(v0, v1);
                    *(__nv_bfloat162*)(Cb + (size_t)row * N + col) = b2;
                }
            }
        }
}

// ============ bf16 GEMM, 128x64 tile (for N = 192) ===========================
__global__ __launch_bounds__(256) void bgemm(
    const __nv_bfloat16* __restrict__ A, const __nv_bfloat16* __restrict__ Bw,
    float* __restrict__ Cf, __nv_bfloat16* __restrict__ Cb,
    int M, int N, int K,
    const float* __restrict__ bias, const float* __restrict__ res, int do_gelu)
{
    __shared__ __align__(16) __nv_bfloat16 As[2][128][ASTR];
    __shared__ __align__(16) __nv_bfloat16 Bs[2][64][ASTR];
    int tid = threadIdx.x, lane = tid & 31, wid = tid >> 5;
    int wm = wid & 3, wn = wid >> 2;
    const __nv_bfloat16* Ab = A  + (size_t)blockIdx.y * 128 * K;
    const __nv_bfloat16* Bb = Bw + (size_t)blockIdx.x * 64 * K;

    float acc[2][4][4];
#pragma unroll
    for (int mf = 0; mf < 2; mf++)
#pragma unroll
        for (int nf = 0; nf < 4; nf++)
#pragma unroll
            for (int i = 0; i < 4; i++) acc[mf][nf][i] = 0.f;

    int nk = K >> 5;
    int lrowA = tid >> 2, lseg = tid & 3;

    {
#pragma unroll
        for (int i = 0; i < 2; i++) {
            int row = lrowA + i * 64;
            cpasync16(smem_u32(&As[0][row][lseg * 8]),
                      Ab + (size_t)row * K + lseg * 8);
        }
        int rowb = tid >> 2;
        if (rowb < 64)
            cpasync16(smem_u32(&Bs[0][rowb][lseg * 8]),
                      Bb + (size_t)rowb * K + lseg * 8);
        CP_COMMIT();
    }

    for (int kc = 0; kc < nk; kc++) {
        int buf = kc & 1;
        if (kc + 1 < nk) {
            int nbuf = buf ^ 1;
            long kb = (long)(kc + 1) * 32;
#pragma unroll
            for (int i = 0; i < 2; i++) {
                int row = lrowA + i * 64;
                cpasync16(smem_u32(&As[nbuf][row][lseg * 8]),
                          Ab + (size_t)row * K + kb + lseg * 8);
            }
            int rowb = tid >> 2;
            if (rowb < 64)
                cpasync16(smem_u32(&Bs[nbuf][rowb][lseg * 8]),
                          Bb + (size_t)rowb * K + kb + lseg * 8);
            CP_COMMIT();
            asm volatile("cp.async.wait_group 1;" ::: "memory");
        } else {
            asm volatile("cp.async.wait_group 0;" ::: "memory");
        }
        __syncthreads();

#pragma unroll
        for (int ks = 0; ks < 2; ks++) {
            unsigned a[2][4], bb[4][2];
#pragma unroll
            for (int mf = 0; mf < 2; mf++) {
                int r = wm * 32 + mf * 16 + (lane & 15);
                int c = ks * 16 + (lane >> 4) * 8;
                ldm_x4(a[mf][0], a[mf][1], a[mf][2], a[mf][3],
                       smem_u32(&As[buf][r][c]));
            }
#pragma unroll
            for (int nh = 0; nh < 2; nh++) {
                int r = wn * 32 + nh * 16 + (lane >> 4) * 8 + (lane & 7);
                int c = ks * 16 + ((lane >> 3) & 1) * 8;
                unsigned r0, r1, r2, r3;
                ldm_x4(r0, r1, r2, r3, smem_u32(&Bs[buf][r][c]));
                bb[nh * 2][0] = r0; bb[nh * 2][1] = r1;
                bb[nh * 2 + 1][0] = r2; bb[nh * 2 + 1][1] = r3;
            }
#pragma unroll
            for (int mf = 0; mf < 2; mf++)
#pragma unroll
                for (int nf = 0; nf < 4; nf++)
                    mma_bf16(acc[mf][nf], a[mf], bb[nf][0], bb[nf][1]);
        }
        __syncthreads();
    }

    int g = lane >> 2, t = lane & 3;
#pragma unroll
    for (int mf = 0; mf < 2; mf++)
#pragma unroll
        for (int nf = 0; nf < 4; nf++) {
            int col = blockIdx.x * 64 + wn * 32 + nf * 8 + 2 * t;
#pragma unroll
            for (int rr = 0; rr < 2; rr++) {
                int row = blockIdx.y * 128 + wm * 32 + mf * 16 + g + rr * 8;
                float v0 = acc[mf][nf][rr * 2 + 0];
                float v1 = acc[mf][nf][rr * 2 + 1];
                if (bias) { v0 += __ldg(&bias[col]); v1 += __ldg(&bias[col + 1]); }
                if (do_gelu) {
                    v0 = 0.5f * v0 * (1.f + erff(v0 * 0.70710678118f));
                    v1 = 0.5f * v1 * (1.f + erff(v1 * 0.70710678118f));
                }
                if (res) {
                    float2 rv = *(const float2*)(res + (size_t)row * N + col);
                    v0 += rv.x; v1 += rv.y;
                }
                if (Cf) {
                    float2 o; o.x = v0; o.y = v1;
                    *(float2*)(Cf + (size_t)row * N + col) = o;
                } else {
                    __nv_bfloat162 b2 = __floats2bfloat162_rn(v0, v1);
                    *(__nv_bfloat162*)(Cb + (size_t)row * N + col) = b2;
                }
            }
        }
}

// ---------------- weight transpose fp32[K,N] -> bf16[N,K] --------------------
__global__ __launch_bounds__(256) void wtrans_kernel(
    const float* __restrict__ W, __nv_bfloat16* __restrict__ Wt, int K, int N)
{
    int i = blockIdx.x * 256 + threadIdx.x;
    if (i >= K * N) return;
    int n = i / K, k = i - n * K;
    Wt[i] = __float2bfloat16(W[(size_t)k * N + n]);
}

// ---------------- depthwise 3x3 conv (correlation, SAME) --------------------
__global__ __launch_bounds__(256) void dwconv_kernel(
    const float* __restrict__ pA, long strideA,
    const float* __restrict__ pB, long strideB,
    const float* __restrict__ w, const float* __restrict__ bias,
    float* __restrict__ out)
{
    int idx = blockIdx.x * 256 + threadIdx.x;
    if (idx >= Bsz * SPLIT * NTOK) return;
    int n = idx % NTOK;
    int c = (idx / NTOK) % SPLIT;
    int b = idx / (NTOK * SPLIT);
    int hh = n / WW, ww = n % WW;
    const float* a  = pA + (size_t)b * strideA + (size_t)c * NTOK;
    const float* bb = pB + (size_t)b * strideB + (size_t)c * NTOK;
    float acc = bias[c];
#pragma unroll
    for (int i = 0; i < 3; i++) {
        int ih = hh + i - 1;
        if (ih < 0 || ih >= HH) continue;
#pragma unroll
        for (int j = 0; j < 3; j++) {
            int iw = ww + j - 1;
            if (iw < 0 || iw >= WW) continue;
            int off = ih * WW + iw;
            acc += w[c * 9 + i * 3 + j] * (a[off] + bb[off]);
        }
    }
    out[idx] = acc;
}

// ------------- assemble token-major x_flat from s0|s1|s2 (tiled transpose) --
__global__ __launch_bounds__(256) void assemble_kernel(const float* __restrict__ x)
{
    __shared__ float tile[32][33];
    int b = blockIdx.z, c0 = blockIdx.y * 32, n0 = blockIdx.x * 32;
    int tx = threadIdx.x, ty = threadIdx.y;
    const float* src;
    if (c0 < 128)      src = x    + ((size_t)b * CDIM  + c0)        * NTOK;
    else if (c0 < 256) src = g_s1 + ((size_t)b * SPLIT + (c0-128)) * NTOK;
    else               src = g_s2 + ((size_t)b * SPLIT + (c0-256)) * NTOK;
#pragma unroll
    for (int r = 0; r < 4; r++)
        tile[ty + r * 8][tx] = src[(size_t)(ty + r * 8) * NTOK + n0 + tx];
    __syncthreads();
#pragma unroll
    for (int r = 0; r < 4; r++)
        g_xf[((size_t)b * NTOK + n0 + ty + r * 8) * CDIM + c0 + tx] = tile[tx][ty + r * 8];
}

// ---------------- LayerNorm over C=384, bf16 output -------------------------
__global__ __launch_bounds__(128) void ln_kernel(
    const float* __restrict__ src, __nv_bfloat16* __restrict__ dst,
    const float* __restrict__ g, const float* __restrict__ bta)
{
    int tok = blockIdx.x;
    const float* r = src + (size_t)tok * CDIM;
    int tid = threadIdx.x;
    float v0 = r[tid], v1 = r[tid + 128], v2 = r[tid + 256];
    float s  = v0 + v1 + v2;
    float s2 = v0 * v0 + v1 * v1 + v2 * v2;
#pragma unroll
    for (int o = 16; o > 0; o >>= 1) {
        s  += __shfl_down_sync(0xFFFFFFFFu, s,  o);
        s2 += __shfl_down_sync(0xFFFFFFFFu, s2, o);
    }
    __shared__ float ss[4], ss2[4];
    int w = tid >> 5;
    if ((tid & 31) == 0) { ss[w] = s; ss2[w] = s2; }
    __syncthreads();
    if (tid == 0) {
        float a  = ss[0] + ss[1] + ss[2] + ss[3];
        float a2 = ss2[0] + ss2[1] + ss2[2] + ss2[3];
        float m  = a / CDIM;
        float var = a2 / CDIM - m * m;
        ss[0] = m; ss2[0] = rsqrtf(var + 1e-6f);
    }
    __syncthreads();
    float m = ss[0], rs = ss2[0];
    __nv_bfloat16* d = dst + (size_t)tok * CDIM;
    d[tid]       = __float2bfloat16((v0 - m) * rs * g[tid]       + bta[tid]);
    d[tid + 128] = __float2bfloat16((v1 - m) * rs * g[tid + 128] + bta[tid + 128]);
    d[tid + 256] = __float2bfloat16((v2 - m) * rs * g[tid + 256] + bta[tid + 256]);
}

// ---------------- XCA attention: one block per (head, batch) ----------------
__global__ __launch_bounds__(256) void attn_kernel()
{
    int h = blockIdx.x, b = blockIdx.y;
    __shared__ float q_s[48][65];
    __shared__ float k_s[48][65];
    __shared__ float attn_s[48][48];
    __shared__ float qn[48], kn[48];
    int tid = threadIdx.x;
    int td = tid >> 4, te = tid & 15;

    float acc[3][3];
#pragma unroll
    for (int i = 0; i < 3; i++)
#pragma unroll
        for (int j = 0; j < 3; j++) acc[i][j] = 0.f;
    float qssl = 0.f, kssl = 0.f;

    for (int n0 = 0; n0 < NTOK; n0 += 64) {
        for (int i = tid; i < 48 * 64; i += 256) {
            int d = i % 48, nn = i / 48;
            size_t base = ((size_t)(b * NTOK + n0 + nn)) * 1152 + h * 48 + d;
            q_s[d][nn] = g_big[base];
            k_s[d][nn] = g_big[base + 384];
        }
        __syncthreads();
        if (tid < 48) {
            float t = 0.f;
#pragma unroll 8
            for (int nn = 0; nn < 64; nn++) { float vv = q_s[tid][nn]; t += vv * vv; }
            qssl += t;
        } else if (tid >= 64 && tid < 112) {
            int d = tid - 64;
            float t = 0.f;
#pragma unroll 8
            for (int nn = 0; nn < 64; nn++) { float vv = k_s[d][nn]; t += vv * vv; }
            kssl += t;
        }
#pragma unroll 4
        for (int nn = 0; nn < 64; nn++) {
            float qa0 = q_s[td * 3 + 0][nn], qa1 = q_s[td * 3 + 1][nn], qa2 = q_s[td * 3 + 2][nn];
            float kb0 = k_s[te * 3 + 0][nn], kb1 = k_s[te * 3 + 1][nn], kb2 = k_s[te * 3 + 2][nn];
            acc[0][0] += qa0 * kb0; acc[0][1] += qa0 * kb1; acc[0][2] += qa0 * kb2;
            acc[1][0] += qa1 * kb0; acc[1][1] += qa1 * kb1; acc[1][2] += qa1 * kb2;
            acc[2][0] += qa2 * kb0; acc[2][1] += qa2 * kb1; acc[2][2] += qa2 * kb2;
        }
        __syncthreads();
    }
    if (tid < 48)                 qn[tid]      = fmaxf(sqrtf(qssl), 1e-12f);
    if (tid >= 64 && tid < 112)   kn[tid - 64] = fmaxf(sqrtf(kssl), 1e-12f);
    __syncthreads();
#pragma unroll
    for (int i = 0; i < 3; i++)
#pragma unroll
        for (int j = 0; j < 3; j++)
            attn_s[td * 3 + i][te * 3 + j] = acc[i][j] / (qn[td * 3 + i] * kn[te * 3 + j]);
    __syncthreads();

    if (tid < 48) {
        float mx = -1e30f;
#pragma unroll 8
        for (int e = 0; e < 48; e++) mx = fmaxf(mx, attn_s[tid][e]);
        float sm = 0.f;
#pragma unroll 8
        for (int e = 0; e < 48; e++) {
            float t = expf(attn_s[tid][e] - mx);
            attn_s[tid][e] = t; sm += t;
        }
        float inv = 1.f / sm;
#pragma unroll 8
        for (int e = 0; e < 48; e++) attn_s[tid][e] *= inv;
    }
    __syncthreads();

    // Phase 2: y = attn @ V, bf16 output (feeds proj GEMM as A operand)
    for (int n0 = 0; n0 < NTOK; n0 += 256) {
        int n = n0 + tid;
        if (n >= NTOK) break;
        size_t base = ((size_t)(b * NTOK + n)) * 1152 + 768 + h * 48;
        float v[48];
#pragma unroll
        for (int i = 0; i < 12; i++) {
            float4 t = *(const float4*)(g_big + base + i * 4);
            v[i * 4 + 0] = t.x; v[i * 4 + 1] = t.y; v[i * 4 + 2] = t.z; v[i * 4 + 3] = t.w;
        }
        __nv_bfloat16* ob = g_att16 + ((size_t)(b * NTOK + n)) * CDIM + h * 48;
#pragma unroll
        for (int d4 = 0; d4 < 12; d4++) {
            float s0 = 0.f, s1 = 0.f, s2 = 0.f, s3 = 0.f;
#pragma unroll
            for (int e = 0; e < 48; e++) {
                float ve = v[e];
                s0 += attn_s[d4 * 4 + 0][e] * ve;
                s1 += attn_s[d4 * 4 + 1][e] * ve;
                s2 += attn_s[d4 * 4 + 2][e] * ve;
                s3 += attn_s[d4 * 4 + 3][e] * ve;
            }
            __nv_bfloat162 p0 = __floats2bfloat162_rn(s0, s1);
            __nv_bfloat162 p1 = __floats2bfloat162_rn(s2, s3);
            uint2 o; o.x = *(unsigned*)&p0; o.y = *(unsigned*)&p1;
            *(uint2*)(ob + d4 * 4) = o;
        }
    }
}

// ---------------- final transpose token-major -> NCHW -----------------------
__global__ __launch_bounds__(256) void to_nchw_kernel(
    const float* __restrict__ src, float* __restrict__ out)
{
    __shared__ float tile[32][33];
    int b = blockIdx.z, c0 = blockIdx.y * 32, n0 = blockIdx.x * 32;
    int tx = threadIdx.x, ty = threadIdx.y;
#pragma unroll
    for (int r = 0; r < 4; r++)
        tile[ty + r * 8][tx] = src[((size_t)b * NTOK + n0 + ty + r * 8) * CDIM + c0 + tx];
    __syncthreads();
#pragma unroll
    for (int r = 0; r < 4; r++)
        out[((size_t)b * CDIM + c0 + ty + r * 8) * NTOK + n0 + tx] = tile[tx][ty + r * 8];
}

// ---------------------------------------------------------------------------
extern "C" void kernel_launch(void* const* d_in, const int* in_sizes, int n_in,
                              void* d_out, int out_size)
{
    const float* x       = (const float*)d_in[0];
    const float* dw_w0   = (const float*)d_in[1];
    const float* dw_b0   = (const float*)d_in[2];
    const float* dw_w1   = (const float*)d_in[3];
    const float* dw_b1   = (const float*)d_in[4];
    const float* ln1_g   = (const float*)d_in[5];
    const float* ln1_b   = (const float*)d_in[6];
    const float* qkv_w   = (const float*)d_in[7];
    const float* proj_w  = (const float*)d_in[8];
    const float* proj_b  = (const float*)d_in[9];
    const float* ln2_g   = (const float*)d_in[10];
    const float* ln2_b   = (const float*)d_in[11];
    const float* mlp1_dw = (const float*)d_in[12];
    const float* mlp1_uw = (const float*)d_in[13];
    const float* mlp1_ub = (const float*)d_in[14];
    const float* mlp2_dw = (const float*)d_in[15];
    const float* mlp2_uw = (const float*)d_in[16];
    const float* mlp2_ub = (const float*)d_in[17];
    float* out = (float*)d_out;

    float *big, *s1, *s2, *xf, *xf2;
    __nv_bfloat16 *y16, *att16, *t116, *t216, *h16;
    __nv_bfloat16 *wq, *wp, *w1d, *w1u, *w2d, *w2u;
    cudaGetSymbolAddress((void**)&big,  g_big);
    cudaGetSymbolAddress((void**)&s1,   g_s1);
    cudaGetSymbolAddress((void**)&s2,   g_s2);
    cudaGetSymbolAddress((void**)&xf,   g_xf);
    cudaGetSymbolAddress((void**)&xf2,  g_xf2);
    cudaGetSymbolAddress((void**)&y16,  g_y16);
    cudaGetSymbolAddress((void**)&att16,g_att16);
    cudaGetSymbolAddress((void**)&t116, g_t116);
    cudaGetSymbolAddress((void**)&t216, g_t216);
    cudaGetSymbolAddress((void**)&h16,  g_h16);
    cudaGetSymbolAddress((void**)&wq,   g_wq);
    cudaGetSymbolAddress((void**)&wp,   g_wp);
    cudaGetSymbolAddress((void**)&w1d,  g_w1d);
    cudaGetSymbolAddress((void**)&w1u,  g_w1u);
    cudaGetSymbolAddress((void**)&w2d,  g_w2d);
    cudaGetSymbolAddress((void**)&w2u,  g_w2u);

    // weight transposes (fp32 [K,N] -> bf16 [N,K])
    wtrans_kernel<<<(384*1152 + 255)/256, 256>>>(qkv_w,  wq,  384, 1152);
    wtrans_kernel<<<(384*384  + 255)/256, 256>>>(proj_w, wp,  384, 384);
    wtrans_kernel<<<(384*192  + 255)/256, 256>>>(mlp1_dw,w1d, 384, 192);
    wtrans_kernel<<<(192*1536 + 255)/256, 256>>>(mlp1_uw,w1u, 192, 1536);
    wtrans_kernel<<<(1536*192 + 255)/256, 256>>>(mlp2_dw,w2d, 1536, 192);
    wtrans_kernel<<<(192*384  + 255)/256, 256>>>(mlp2_uw,w2u, 192, 384);

    int nconv = Bsz * SPLIT * NTOK;
    int cblk = (nconv + 255) / 256;

    dwconv_kernel<<<cblk, 256>>>(x, (long)CDIM * NTOK,
                                 x + (size_t)SPLIT * NTOK, (long)CDIM * NTOK,
                                 dw_w0, dw_b0, s1);
    dwconv_kernel<<<cblk, 256>>>(s1, (long)SPLIT * NTOK,
                                 x + (size_t)2 * SPLIT * NTOK, (long)CDIM * NTOK,
                                 dw_w1, dw_b1, s2);

    assemble_kernel<<<dim3(98, 12, Bsz), dim3(32, 8)>>>(x);

    ln_kernel<<<TOKS, 128>>>(xf, y16, ln1_g, ln1_b);

    // qkv = y @ qkv_w  [TOKS, 1152]  (fp32 out into g_big)
    bgemm128<<<dim3(1152/128, TOKS/128), 256>>>(y16, wq, big, nullptr,
                                                TOKS, 1152, 384, nullptr, nullptr, 0);

    attn_kernel<<<dim3(NHEAD, Bsz), 256>>>();

    // xf2 = xf + att @ proj_w + proj_b   (fp32 out)
    bgemm128<<<dim3(384/128, TOKS/128), 256>>>(att16, wp, xf2, nullptr,
                                               TOKS, 384, 384, proj_b, xf, 0);

    ln_kernel<<<TOKS, 128>>>(xf2, y16, ln2_g, ln2_b);

    // t1 = y @ mlp1_dw (bf16 out); h = gelu(t1 @ mlp1_uw + b) (bf16 out)
    bgemm<<<dim3(192/64, TOKS/128), 256>>>(y16, w1d, nullptr, t116,
                                           TOKS, 192, 384, nullptr, nullptr, 0);
    bgemm128<<<dim3(1536/128, TOKS/128), 256>>>(t116, w1u, nullptr, h16,
                                                TOKS, 1536, 192, mlp1_ub, nullptr, 1);
    // t2 = h @ mlp2_dw (bf16); final = xf2 + t2 @ mlp2_uw + b (fp32, into g_big)
    bgemm<<<dim3(192/64, TOKS/128), 256>>>(h16, w2d, nullptr, t216,
                                           TOKS, 192, 1536, nullptr, nullptr, 0);
    bgemm128<<<dim3(384/128, TOKS/128), 256>>>(t216, w2u, big, nullptr,
                                               TOKS, 384, 192, mlp2_ub, xf2, 0);

    to_nchw_kernel<<<dim3(98, 12, Bsz), dim3(32, 8)>>>(big, out);

    (void)in_sizes; (void)n_in; (void)out_size;
}

// round 9
// speedup vs baseline: 3.0109x; 1.0454x over previous
#include <cuda_runtime.h>
#include <cuda_bf16.h>
#include <math.h>

#define Bsz   16
#define CDIM  384
#define HH    56
#define WW    56
#define NTOK  3136          // 56*56
#define TOKS  (Bsz*NTOK)    // 50176
#define NHEAD 8
#define SPLIT 128
#define HID   1536
#define RR    192

// ---------------- scratch (device globals; no allocations allowed) ----------
// g_big: first used as bf16 qkv [TOKS*1152] (via alias), later as fp32 final out
__device__ float g_big[(size_t)TOKS*1152];
__device__ float g_s1 [(size_t)Bsz*SPLIT*NTOK];
__device__ float g_s2 [(size_t)Bsz*SPLIT*NTOK];
__device__ float g_xf [(size_t)TOKS*CDIM];
__device__ float g_xf2[(size_t)TOKS*CDIM];
__device__ __nv_bfloat16 g_y16 [(size_t)TOKS*CDIM];
__device__ __nv_bfloat16 g_att16[(size_t)TOKS*CDIM];
__device__ __nv_bfloat16 g_t116[(size_t)TOKS*RR];
__device__ __nv_bfloat16 g_t216[(size_t)TOKS*RR];
__device__ __nv_bfloat16 g_h16 [(size_t)TOKS*HID];
// transposed bf16 weights, [N, K] K-major rows
__device__ __nv_bfloat16 g_wq [1152*384];
__device__ __nv_bfloat16 g_wp [384*384];
__device__ __nv_bfloat16 g_w1d[192*384];
__device__ __nv_bfloat16 g_w1u[1536*192];
__device__ __nv_bfloat16 g_w2d[192*1536];
__device__ __nv_bfloat16 g_w2u[384*192];

// ---------------- helpers ----------------------------------------------------
__device__ __forceinline__ unsigned smem_u32(const void* p) {
    unsigned a;
    asm("{ .reg .u64 t; cvta.to.shared.u64 t, %1; cvt.u32.u64 %0, t; }"
        : "=r"(a) : "l"(p));
    return a;
}
__device__ __forceinline__ void cpasync16(unsigned dst, const void* src) {
    asm volatile("cp.async.cg.shared.global [%0], [%1], 16;" :: "r"(dst), "l"(src));
}
#define CP_COMMIT() asm volatile("cp.async.commit_group;" ::: "memory")
__device__ __forceinline__ void ldm_x4(unsigned& r0, unsigned& r1, unsigned& r2,
                                       unsigned& r3, unsigned addr) {
    asm volatile("ldmatrix.sync.aligned.m8n8.x4.shared.b16 {%0,%1,%2,%3}, [%4];"
                 : "=r"(r0), "=r"(r1), "=r"(r2), "=r"(r3) : "r"(addr));
}
__device__ __forceinline__ void mma_bf16(float* d, const unsigned* a,
                                         unsigned b0, unsigned b1) {
    asm volatile(
        "mma.sync.aligned.m16n8k16.row.col.f32.bf16.bf16.f32 "
        "{%0,%1,%2,%3}, {%4,%5,%6,%7}, {%8,%9}, {%0,%1,%2,%3};\n"
        : "+f"(d[0]), "+f"(d[1]), "+f"(d[2]), "+f"(d[3])
        : "r"(a[0]), "r"(a[1]), "r"(a[2]), "r"(a[3]), "r"(b0), "r"(b1));
}

#define ASTR 40   // padded row stride (bf16): 32 data + 8 pad -> conflict-free ldmatrix

// ============ bf16 GEMM, 128x128 tile (N % 128 == 0), 3-stage pipeline =======
// 8 warps as 2x4: warp tile 64x32. K-chunk 32, one __syncthreads per chunk.
__global__ __launch_bounds__(256) void bgemm128(
    const __nv_bfloat16* __restrict__ A, const __nv_bfloat16* __restrict__ Bw,
    float* __restrict__ Cf, __nv_bfloat16* __restrict__ Cb,
    int M, int N, int K,
    const float* __restrict__ bias, const float* __restrict__ res, int do_gelu)
{
    __shared__ __align__(16) __nv_bfloat16 As[3][128][ASTR];
    __shared__ __align__(16) __nv_bfloat16 Bs[3][128][ASTR];
    int tid = threadIdx.x, lane = tid & 31, wid = tid >> 5;
    int wm = wid & 1, wn = wid >> 1;          // 2 x 4 warp grid
    const __nv_bfloat16* Ab = A  + (size_t)blockIdx.y * 128 * K;
    const __nv_bfloat16* Bb = Bw + (size_t)blockIdx.x * 128 * K;

    float acc[4][4][4];
#pragma unroll
    for (int mf = 0; mf < 4; mf++)
#pragma unroll
        for (int nf = 0; nf < 4; nf++)
#pragma unroll
            for (int i = 0; i < 4; i++) acc[mf][nf][i] = 0.f;

    int nk = K >> 5;
    int lrow = tid >> 2, lseg = tid & 3;

    // prologue: chunks 0,1 into bufs 0,1 (nk >= 2 always: K >= 192)
#pragma unroll
    for (int pc = 0; pc < 2; pc++) {
        long kb = (long)pc * 32;
#pragma unroll
        for (int i = 0; i < 2; i++) {
            int row = lrow + i * 64;
            cpasync16(smem_u32(&As[pc][row][lseg * 8]), Ab + (size_t)row * K + kb + lseg * 8);
            cpasync16(smem_u32(&Bs[pc][row][lseg * 8]), Bb + (size_t)row * K + kb + lseg * 8);
        }
        CP_COMMIT();
    }

    for (int kc = 0; kc < nk; kc++) {
        int buf = kc % 3;
        if (kc + 1 < nk) asm volatile("cp.async.wait_group 1;" ::: "memory");
        else             asm volatile("cp.async.wait_group 0;" ::: "memory");
        __syncthreads();
        if (kc + 2 < nk) {
            int nbuf = (kc + 2) % 3;
            long kb = (long)(kc + 2) * 32;
#pragma unroll
            for (int i = 0; i < 2; i++) {
                int row = lrow + i * 64;
                cpasync16(smem_u32(&As[nbuf][row][lseg * 8]),
                          Ab + (size_t)row * K + kb + lseg * 8);
                cpasync16(smem_u32(&Bs[nbuf][row][lseg * 8]),
                          Bb + (size_t)row * K + kb + lseg * 8);
            }
            CP_COMMIT();
        }

#pragma unroll
        for (int ks = 0; ks < 2; ks++) {
            unsigned a[4][4], bb[4][2];
#pragma unroll
            for (int mf = 0; mf < 4; mf++) {
                int r = wm * 64 + mf * 16 + (lane & 15);
                int c = ks * 16 + (lane >> 4) * 8;
                ldm_x4(a[mf][0], a[mf][1], a[mf][2], a[mf][3],
                       smem_u32(&As[buf][r][c]));
            }
#pragma unroll
            for (int nh = 0; nh < 2; nh++) {
                int r = wn * 32 + nh * 16 + (lane >> 4) * 8 + (lane & 7);
                int c = ks * 16 + ((lane >> 3) & 1) * 8;
                unsigned r0, r1, r2, r3;
                ldm_x4(r0, r1, r2, r3, smem_u32(&Bs[buf][r][c]));
                bb[nh * 2][0] = r0; bb[nh * 2][1] = r1;
                bb[nh * 2 + 1][0] = r2; bb[nh * 2 + 1][1] = r3;
            }
#pragma unroll
            for (int mf = 0; mf < 4; mf++)
#pragma unroll
                for (int nf = 0; nf < 4; nf++)
                    mma_bf16(acc[mf][nf], a[mf], bb[nf][0], bb[nf][1]);
        }
    }

    // epilogue
    int g = lane >> 2, t = lane & 3;
#pragma unroll
    for (int mf = 0; mf < 4; mf++)
#pragma unroll
        for (int nf = 0; nf < 4; nf++) {
            int col = blockIdx.x * 128 + wn * 32 + nf * 8 + 2 * t;
#pragma unroll
            for (int rr = 0; rr < 2; rr++) {
                int row = blockIdx.y * 128 + wm * 64 + mf * 16 + g + rr * 8;
                float v0 = acc[mf][nf][rr * 2 + 0];
                float v1 = acc[mf][nf][rr * 2 + 1];
                if (bias) { v0 += __ldg(&bias[col]); v1 += __ldg(&bias[col + 1]); }
                if (do_gelu) {
                    v0 = 0.5f * v0 * (1.f + erff(v0 * 0.70710678118f));
                    v1 = 0.5f * v1 * (1.f + erff(v1 * 0.70710678118f));
                }
                if (res) {
                    float2 rv = *(const float2*)(res + (size_t)row * N + col);
                    v0 += rv.x; v1 += rv.y;
                }
                if (Cf) {
                    float2 o; o.x = v0; o.y = v1;
                    *(float2*)(Cf + (size_t)row * N + col) = o;
                } else {
                    __nv_bfloat162 b2 = __floats2bfloat162_rn(v0, v1);
                    *(__nv_bfloat162*)(Cb + (size_t)row * N + col) = b2;
                }
            }
        }
}

// ============ bf16 GEMM, 128x64 tile (for N = 192), 3-stage pipeline =========
__global__ __launch_bounds__(256) void bgemm(
    const __nv_bfloat16* __restrict__ A, const __nv_bfloat16* __restrict__ Bw,
    float* __restrict__ Cf, __nv_bfloat16* __restrict__ Cb,
    int M, int N, int K,
    const float* __restrict__ bias, const float* __restrict__ res, int do_gelu)
{
    __shared__ __align__(16) __nv_bfloat16 As[3][128][ASTR];
    __shared__ __align__(16) __nv_bfloat16 Bs[3][64][ASTR];
    int tid = threadIdx.x, lane = tid & 31, wid = tid >> 5;
    int wm = wid & 3, wn = wid >> 2;
    const __nv_bfloat16* Ab = A  + (size_t)blockIdx.y * 128 * K;
    const __nv_bfloat16* Bb = Bw + (size_t)blockIdx.x * 64 * K;

    float acc[2][4][4];
#pragma unroll
    for (int mf = 0; mf < 2; mf++)
#pragma unroll
        for (int nf = 0; nf < 4; nf++)
#pragma unroll
            for (int i = 0; i < 4; i++) acc[mf][nf][i] = 0.f;

    int nk = K >> 5;
    int lrow = tid >> 2, lseg = tid & 3;

#pragma unroll
    for (int pc = 0; pc < 2; pc++) {
        long kb = (long)pc * 32;
#pragma unroll
        for (int i = 0; i < 2; i++) {
            int row = lrow + i * 64;
            cpasync16(smem_u32(&As[pc][row][lseg * 8]),
                      Ab + (size_t)row * K + kb + lseg * 8);
        }
        if (lrow < 64)
            cpasync16(smem_u32(&Bs[pc][lrow][lseg * 8]),
                      Bb + (size_t)lrow * K + kb + lseg * 8);
        CP_COMMIT();
    }

    for (int kc = 0; kc < nk; kc++) {
        int buf = kc % 3;
        if (kc + 1 < nk) asm volatile("cp.async.wait_group 1;" ::: "memory");
        else             asm volatile("cp.async.wait_group 0;" ::: "memory");
        __syncthreads();
        if (kc + 2 < nk) {
            int nbuf = (kc + 2) % 3;
            long kb = (long)(kc + 2) * 32;
#pragma unroll
            for (int i = 0; i < 2; i++) {
                int row = lrow + i * 64;
                cpasync16(smem_u32(&As[nbuf][row][lseg * 8]),
                          Ab + (size_t)row * K + kb + lseg * 8);
            }
            if (lrow < 64)
                cpasync16(smem_u32(&Bs[nbuf][lrow][lseg * 8]),
                          Bb + (size_t)lrow * K + kb + lseg * 8);
            CP_COMMIT();
        }

#pragma unroll
        for (int ks = 0; ks < 2; ks++) {
            unsigned a[2][4], bb[4][2];
#pragma unroll
            for (int mf = 0; mf < 2; mf++) {
                int r = wm * 32 + mf * 16 + (lane & 15);
                int c = ks * 16 + (lane >> 4) * 8;
                ldm_x4(a[mf][0], a[mf][1], a[mf][2], a[mf][3],
                       smem_u32(&As[buf][r][c]));
            }
#pragma unroll
            for (int nh = 0; nh < 2; nh++) {
                int r = wn * 32 + nh * 16 + (lane >> 4) * 8 + (lane & 7);
                int c = ks * 16 + ((lane >> 3) & 1) * 8;
                unsigned r0, r1, r2, r3;
                ldm_x4(r0, r1, r2, r3, smem_u32(&Bs[buf][r][c]));
                bb[nh * 2][0] = r0; bb[nh * 2][1] = r1;
                bb[nh * 2 + 1][0] = r2; bb[nh * 2 + 1][1] = r3;
            }
#pragma unroll
            for (int mf = 0; mf < 2; mf++)
#pragma unroll
                for (int nf = 0; nf < 4; nf++)
                    mma_bf16(acc[mf][nf], a[mf], bb[nf][0], bb[nf][1]);
        }
    }

    int g = lane >> 2, t = lane & 3;
#pragma unroll
    for (int mf = 0; mf < 2; mf++)
#pragma unroll
        for (int nf = 0; nf < 4; nf++) {
            int col = blockIdx.x * 64 + wn * 32 + nf * 8 + 2 * t;
#pragma unroll
            for (int rr = 0; rr < 2; rr++) {
                int row = blockIdx.y * 128 + wm * 32 + mf * 16 + g + rr * 8;
                float v0 = acc[mf][nf][rr * 2 + 0];
                float v1 = acc[mf][nf][rr * 2 + 1];
                if (bias) { v0 += __ldg(&bias[col]); v1 += __ldg(&bias[col + 1]); }
                if (do_gelu) {
                    v0 = 0.5f * v0 * (1.f + erff(v0 * 0.70710678118f));
                    v1 = 0.5f * v1 * (1.f + erff(v1 * 0.70710678118f));
                }
                if (res) {
                    float2 rv = *(const float2*)(res + (size_t)row * N + col);
                    v0 += rv.x; v1 += rv.y;
                }
                if (Cf) {
                    float2 o; o.x = v0; o.y = v1;
                    *(float2*)(Cf + (size_t)row * N + col) = o;
                } else {
                    __nv_bfloat162 b2 = __floats2bfloat162_rn(v0, v1);
                    *(__nv_bfloat162*)(Cb + (size_t)row * N + col) = b2;
                }
            }
        }
}

// ---------------- all weight transposes fp32[K,N] -> bf16[N,K], one launch ---
#define WT0 442368    // qkv  1152x384
#define WT1 589824    // proj  384x384
#define WT2 663552    // m1d   192x384
#define WT3 958464    // m1u  1536x192
#define WT4 1253376   // m2d   192x1536
#define WT5 1327104   // m2u   384x192
__global__ __launch_bounds__(256) void wtrans_all(
    const float* __restrict__ w0, const float* __restrict__ w1,
    const float* __restrict__ w2, const float* __restrict__ w3,
    const float* __restrict__ w4, const float* __restrict__ w5)
{
    int i = blockIdx.x * 256 + threadIdx.x;
    if (i >= WT5) return;
    const float* s; __nv_bfloat16* d; int off, K;
    if      (i < WT0) { s = w0; d = g_wq;  off = 0;   K = 384; }
    else if (i < WT1) { s = w1; d = g_wp;  off = WT0; K = 384; }
    else if (i < WT2) { s = w2; d = g_w1d; off = WT1; K = 384; }
    else if (i < WT3) { s = w3; d = g_w1u; off = WT2; K = 192; }
    else if (i < WT4) { s = w4; d = g_w2d; off = WT3; K = 1536; }
    else              { s = w5; d = g_w2u; off = WT4; K = 192; }
    int j = i - off;
    int n = j / K, k = j - n * K;
    int N = (i < WT0) ? 1152 : (i < WT1) ? 384 : (i < WT2) ? 192 :
            (i < WT3) ? 1536 : (i < WT4) ? 192 : 384;
    d[j] = __float2bfloat16(s[(size_t)k * N + n]);
}

// ---------------- depthwise 3x3 conv (correlation, SAME) --------------------
__global__ __launch_bounds__(256) void dwconv_kernel(
    const float* __restrict__ pA, long strideA,
    const float* __restrict__ pB, long strideB,
    const float* __restrict__ w, const float* __restrict__ bias,
    float* __restrict__ out)
{
    int idx = blockIdx.x * 256 + threadIdx.x;
    if (idx >= Bsz * SPLIT * NTOK) return;
    int n = idx % NTOK;
    int c = (idx / NTOK) % SPLIT;
    int b = idx / (NTOK * SPLIT);
    int hh = n / WW, ww = n % WW;
    const float* a  = pA + (size_t)b * strideA + (size_t)c * NTOK;
    const float* bb = pB + (size_t)b * strideB + (size_t)c * NTOK;
    float acc = bias[c];
#pragma unroll
    for (int i = 0; i < 3; i++) {
        int ih = hh + i - 1;
        if (ih < 0 || ih >= HH) continue;
#pragma unroll
        for (int j = 0; j < 3; j++) {
            int iw = ww + j - 1;
            if (iw < 0 || iw >= WW) continue;
            int off = ih * WW + iw;
            acc += w[c * 9 + i * 3 + j] * (a[off] + bb[off]);
        }
    }
    out[idx] = acc;
}

// ------------- assemble token-major x_flat from s0|s1|s2 (tiled transpose) --
__global__ __launch_bounds__(256) void assemble_kernel(const float* __restrict__ x)
{
    __shared__ float tile[32][33];
    int b = blockIdx.z, c0 = blockIdx.y * 32, n0 = blockIdx.x * 32;
    int tx = threadIdx.x, ty = threadIdx.y;
    const float* src;
    if (c0 < 128)      src = x    + ((size_t)b * CDIM  + c0)        * NTOK;
    else if (c0 < 256) src = g_s1 + ((size_t)b * SPLIT + (c0-128)) * NTOK;
    else               src = g_s2 + ((size_t)b * SPLIT + (c0-256)) * NTOK;
#pragma unroll
    for (int r = 0; r < 4; r++)
        tile[ty + r * 8][tx] = src[(size_t)(ty + r * 8) * NTOK + n0 + tx];
    __syncthreads();
#pragma unroll
    for (int r = 0; r < 4; r++)
        g_xf[((size_t)b * NTOK + n0 + ty + r * 8) * CDIM + c0 + tx] = tile[tx][ty + r * 8];
}

// ---------------- LayerNorm over C=384, bf16 output -------------------------
__global__ __launch_bounds__(128) void ln_kernel(
    const float* __restrict__ src, __nv_bfloat16* __restrict__ dst,
    const float* __restrict__ g, const float* __restrict__ bta)
{
    int tok = blockIdx.x;
    const float* r = src + (size_t)tok * CDIM;
    int tid = threadIdx.x;
    float v0 = r[tid], v1 = r[tid + 128], v2 = r[tid + 256];
    float s  = v0 + v1 + v2;
    float s2 = v0 * v0 + v1 * v1 + v2 * v2;
#pragma unroll
    for (int o = 16; o > 0; o >>= 1) {
        s  += __shfl_down_sync(0xFFFFFFFFu, s,  o);
        s2 += __shfl_down_sync(0xFFFFFFFFu, s2, o);
    }
    __shared__ float ss[4], ss2[4];
    int w = tid >> 5;
    if ((tid & 31) == 0) { ss[w] = s; ss2[w] = s2; }
    __syncthreads();
    if (tid == 0) {
        float a  = ss[0] + ss[1] + ss[2] + ss[3];
        float a2 = ss2[0] + ss2[1] + ss2[2] + ss2[3];
        float m  = a / CDIM;
        float var = a2 / CDIM - m * m;
        ss[0] = m; ss2[0] = rsqrtf(var + 1e-6f);
    }
    __syncthreads();
    float m = ss[0], rs = ss2[0];
    __nv_bfloat16* d = dst + (size_t)tok * CDIM;
    d[tid]       = __float2bfloat16((v0 - m) * rs * g[tid]       + bta[tid]);
    d[tid + 128] = __float2bfloat16((v1 - m) * rs * g[tid + 128] + bta[tid + 128]);
    d[tid + 256] = __float2bfloat16((v2 - m) * rs * g[tid + 256] + bta[tid + 256]);
}

// ---------------- XCA attention: one block per (head, batch), bf16 qkv ------
__global__ __launch_bounds__(256) void attn_kernel()
{
    const __nv_bfloat16* qkv16 = (const __nv_bfloat16*)g_big;
    int h = blockIdx.x, b = blockIdx.y;
    __shared__ float q_s[48][65];
    __shared__ float k_s[48][65];
    __shared__ float attn_s[48][48];
    __shared__ float qn[48], kn[48];
    int tid = threadIdx.x;
    int td = tid >> 4, te = tid & 15;

    float acc[3][3];
#pragma unroll
    for (int i = 0; i < 3; i++)
#pragma unroll
        for (int j = 0; j < 3; j++) acc[i][j] = 0.f;
    float qssl = 0.f, kssl = 0.f;

    for (int n0 = 0; n0 < NTOK; n0 += 64) {
        for (int i = tid; i < 48 * 64; i += 256) {
            int d = i % 48, nn = i / 48;
            size_t base = ((size_t)(b * NTOK + n0 + nn)) * 1152 + h * 48 + d;
            q_s[d][nn] = __bfloat162float(qkv16[base]);
            k_s[d][nn] = __bfloat162float(qkv16[base + 384]);
        }
        __syncthreads();
        if (tid < 48) {
            float t = 0.f;
#pragma unroll 8
            for (int nn = 0; nn < 64; nn++) { float vv = q_s[tid][nn]; t += vv * vv; }
            qssl += t;
        } else if (tid >= 64 && tid < 112) {
            int d = tid - 64;
            float t = 0.f;
#pragma unroll 8
            for (int nn = 0; nn < 64; nn++) { float vv = k_s[d][nn]; t += vv * vv; }
            kssl += t;
        }
#pragma unroll 4
        for (int nn = 0; nn < 64; nn++) {
            float qa0 = q_s[td * 3 + 0][nn], qa1 = q_s[td * 3 + 1][nn], qa2 = q_s[td * 3 + 2][nn];
            float kb0 = k_s[te * 3 + 0][nn], kb1 = k_s[te * 3 + 1][nn], kb2 = k_s[te * 3 + 2][nn];
            acc[0][0] += qa0 * kb0; acc[0][1] += qa0 * kb1; acc[0][2] += qa0 * kb2;
            acc[1][0] += qa1 * kb0; acc[1][1] += qa1 * kb1; acc[1][2] += qa1 * kb2;
            acc[2][0] += qa2 * kb0; acc[2][1] += qa2 * kb1; acc[2][2] += qa2 * kb2;
        }
        __syncthreads();
    }
    if (tid < 48)                 qn[tid]      = fmaxf(sqrtf(qssl), 1e-12f);
    if (tid >= 64 && tid < 112)   kn[tid - 64] = fmaxf(sqrtf(kssl), 1e-12f);
    __syncthreads();
#pragma unroll
    for (int i = 0; i < 3; i++)
#pragma unroll
        for (int j = 0; j < 3; j++)
            attn_s[td * 3 + i][te * 3 + j] = acc[i][j] / (qn[td * 3 + i] * kn[te * 3 + j]);
    __syncthreads();

    if (tid < 48) {
        float mx = -1e30f;
#pragma unroll 8
        for (int e = 0; e < 48; e++) mx = fmaxf(mx, attn_s[tid][e]);
        float sm = 0.f;
#pragma unroll 8
        for (int e = 0; e < 48; e++) {
            float t = expf(attn_s[tid][e] - mx);
            attn_s[tid][e] = t; sm += t;
        }
        float inv = 1.f / sm;
#pragma unroll 8
        for (int e = 0; e < 48; e++) attn_s[tid][e] *= inv;
    }
    __syncthreads();

    // Phase 2: y = attn @ V (bf16 V), bf16 output
    for (int n0 = 0; n0 < NTOK; n0 += 256) {
        int n = n0 + tid;
        if (n >= NTOK) break;
        size_t base = ((size_t)(b * NTOK + n)) * 1152 + 768 + h * 48;
        const uint4* vp = (const uint4*)(qkv16 + base);
        float v[48];
#pragma unroll
        for (int i = 0; i < 6; i++) {
            uint4 t = vp[i];
            unsigned wrd[4] = { t.x, t.y, t.z, t.w };
#pragma unroll
            for (int q = 0; q < 4; q++) {
                __nv_bfloat162 b2 = *(__nv_bfloat162*)&wrd[q];
                v[i * 8 + q * 2 + 0] = __low2float(b2);
                v[i * 8 + q * 2 + 1] = __high2float(b2);
            }
        }
        __nv_bfloat16* ob = g_att16 + ((size_t)(b * NTOK + n)) * CDIM + h * 48;
#pragma unroll
        for (int d4 = 0; d4 < 12; d4++) {
            float s0 = 0.f, s1 = 0.f, s2 = 0.f, s3 = 0.f;
#pragma unroll
            for (int e = 0; e < 48; e++) {
                float ve = v[e];
                s0 += attn_s[d4 * 4 + 0][e] * ve;
                s1 += attn_s[d4 * 4 + 1][e] * ve;
                s2 += attn_s[d4 * 4 + 2][e] * ve;
                s3 += attn_s[d4 * 4 + 3][e] * ve;
            }
            __nv_bfloat162 p0 = __floats2bfloat162_rn(s0, s1);
            __nv_bfloat162 p1 = __floats2bfloat162_rn(s2, s3);
            uint2 o; o.x = *(unsigned*)&p0; o.y = *(unsigned*)&p1;
            *(uint2*)(ob + d4 * 4) = o;
        }
    }
}

// ---------------- final transpose token-major -> NCHW -----------------------
__global__ __launch_bounds__(256) void to_nchw_kernel(
    const float* __restrict__ src, float* __restrict__ out)
{
    __shared__ float tile[32][33];
    int b = blockIdx.z, c0 = blockIdx.y * 32, n0 = blockIdx.x * 32;
    int tx = threadIdx.x, ty = threadIdx.y;
#pragma unroll
    for (int r = 0; r < 4; r++)
        tile[ty + r * 8][tx] = src[((size_t)b * NTOK + n0 + ty + r * 8) * CDIM + c0 + tx];
    __syncthreads();
#pragma unroll
    for (int r = 0; r < 4; r++)
        out[((size_t)b * CDIM + c0 + ty + r * 8) * NTOK + n0 + tx] = tile[tx][ty + r * 8];
}

// ---------------------------------------------------------------------------
extern "C" void kernel_launch(void* const* d_in, const int* in_sizes, int n_in,
                              void* d_out, int out_size)
{
    const float* x       = (const float*)d_in[0];
    const float* dw_w0   = (const float*)d_in[1];
    const float* dw_b0   = (const float*)d_in[2];
    const float* dw_w1   = (const float*)d_in[3];
    const float* dw_b1   = (const float*)d_in[4];
    const float* ln1_g   = (const float*)d_in[5];
    const float* ln1_b   = (const float*)d_in[6];
    const float* qkv_w   = (const float*)d_in[7];
    const float* proj_w  = (const float*)d_in[8];
    const float* proj_b  = (const float*)d_in[9];
    const float* ln2_g   = (const float*)d_in[10];
    const float* ln2_b   = (const float*)d_in[11];
    const float* mlp1_dw = (const float*)d_in[12];
    const float* mlp1_uw = (const float*)d_in[13];
    const float* mlp1_ub = (const float*)d_in[14];
    const float* mlp2_dw = (const float*)d_in[15];
    const float* mlp2_uw = (const float*)d_in[16];
    const float* mlp2_ub = (const float*)d_in[17];
    float* out = (float*)d_out;

    float *big, *s1, *s2, *xf, *xf2;
    __nv_bfloat16 *y16, *att16, *t116, *t216, *h16;
    __nv_bfloat16 *wq, *wp, *w1d, *w1u, *w2d, *w2u;
    cudaGetSymbolAddress((void**)&big,  g_big);
    cudaGetSymbolAddress((void**)&s1,   g_s1);
    cudaGetSymbolAddress((void**)&s2,   g_s2);
    cudaGetSymbolAddress((void**)&xf,   g_xf);
    cudaGetSymbolAddress((void**)&xf2,  g_xf2);
    cudaGetSymbolAddress((void**)&y16,  g_y16);
    cudaGetSymbolAddress((void**)&att16,g_att16);
    cudaGetSymbolAddress((void**)&t116, g_t116);
    cudaGetSymbolAddress((void**)&t216, g_t216);
    cudaGetSymbolAddress((void**)&h16,  g_h16);
    cudaGetSymbolAddress((void**)&wq,   g_wq);
    cudaGetSymbolAddress((void**)&wp,   g_wp);
    cudaGetSymbolAddress((void**)&w1d,  g_w1d);
    cudaGetSymbolAddress((void**)&w1u,  g_w1u);
    cudaGetSymbolAddress((void**)&w2d,  g_w2d);
    cudaGetSymbolAddress((void**)&w2u,  g_w2u);
    __nv_bfloat16* qkv16 = (__nv_bfloat16*)big;   // bf16 alias, lifetime ends at attn

    // all weight transposes in one launch
    wtrans_all<<<(WT5 + 255) / 256, 256>>>(qkv_w, proj_w, mlp1_dw, mlp1_uw,
                                           mlp2_dw, mlp2_uw);

    int nconv = Bsz * SPLIT * NTOK;
    int cblk = (nconv + 255) / 256;

    dwconv_kernel<<<cblk, 256>>>(x, (long)CDIM * NTOK,
                                 x + (size_t)SPLIT * NTOK, (long)CDIM * NTOK,
                                 dw_w0, dw_b0, s1);
    dwconv_kernel<<<cblk, 256>>>(s1, (long)SPLIT * NTOK,
                                 x + (size_t)2 * SPLIT * NTOK, (long)CDIM * NTOK,
                                 dw_w1, dw_b1, s2);

    assemble_kernel<<<dim3(98, 12, Bsz), dim3(32, 8)>>>(x);

    ln_kernel<<<TOKS, 128>>>(xf, y16, ln1_g, ln1_b);

    // qkv = y @ qkv_w  [TOKS, 1152]  (bf16 out into g_big alias)
    bgemm128<<<dim3(1152/128, TOKS/128), 256>>>(y16, wq, nullptr, qkv16,
                                                TOKS, 1152, 384, nullptr, nullptr, 0);

    attn_kernel<<<dim3(NHEAD, Bsz), 256>>>();

    // xf2 = xf + att @ proj_w + proj_b   (fp32 out)
    bgemm128<<<dim3(384/128, TOKS/128), 256>>>(att16, wp, xf2, nullptr,
                                               TOKS, 384, 384, proj_b, xf, 0);

    ln_kernel<<<TOKS, 128>>>(xf2, y16, ln2_g, ln2_b);

    // t1 = y @ mlp1_dw (bf16 out); h = gelu(t1 @ mlp1_uw + b) (bf16 out)
    bgemm<<<dim3(192/64, TOKS/128), 256>>>(y16, w1d, nullptr, t116,
                                           TOKS, 192, 384, nullptr, nullptr, 0);
    bgemm128<<<dim3(1536/128, TOKS/128), 256>>>(t116, w1u, nullptr, h16,
                                                TOKS, 1536, 192, mlp1_ub, nullptr, 1);
    // t2 = h @ mlp2_dw (bf16); final = xf2 + t2 @ mlp2_uw + b (fp32, into g_big)
    bgemm<<<dim3(192/64, TOKS/128), 256>>>(h16, w2d, nullptr, t216,
                                           TOKS, 192, 1536, nullptr, nullptr, 0);
    bgemm128<<<dim3(384/128, TOKS/128), 256>>>(t216, w2u, big, nullptr,
                                               TOKS, 384, 192, mlp2_ub, xf2, 0);

    to_nchw_kernel<<<dim3(98, 12, Bsz), dim3(32, 8)>>>(big, out);

    (void)in_sizes; (void)n_in; (void)out_size;
}

// round 12
// speedup vs baseline: 3.1863x; 1.0583x over previous
#include <cuda_runtime.h>
#include <cuda_bf16.h>
#include <math.h>

#define Bsz   16
#define CDIM  384
#define HH    56
#define WW    56
#define NTOK  3136          // 56*56
#define TOKS  (Bsz*NTOK)    // 50176
#define NHEAD 8
#define SPLIT 128
#define HID   1536
#define RR    192
#define NSPL  7             // attention token splits (49 tiles of 64 = 7x7)

typedef unsigned long long ull;

// ---------------- scratch (device globals; no allocations allowed) ----------
__device__ float g_big[(size_t)TOKS*1152];     // bf16 qkv alias lives here
__device__ float g_s1 [(size_t)Bsz*SPLIT*NTOK];
__device__ float g_s2 [(size_t)Bsz*SPLIT*NTOK];
__device__ float g_xf [(size_t)TOKS*CDIM];
__device__ float g_xf2[(size_t)TOKS*CDIM];
__device__ __nv_bfloat16 g_y16 [(size_t)TOKS*CDIM];
__device__ __nv_bfloat16 g_att16[(size_t)TOKS*CDIM];
__device__ __nv_bfloat16 g_t116[(size_t)TOKS*RR];
__device__ __nv_bfloat16 g_t216[(size_t)TOKS*RR];
__device__ __nv_bfloat16 g_h16 [(size_t)TOKS*HID];
// attention staging
__device__ float  g_gramP[(size_t)NSPL*128*2304];
__device__ float  g_qsqP [(size_t)NSPL*128*48];
__device__ float  g_ksqP [(size_t)NSPL*128*48];
__device__ float2 g_attn2[(size_t)128*2304];
// transposed bf16 weights, [N, K] K-major rows
__device__ __nv_bfloat16 g_wq [1152*384];
__device__ __nv_bfloat16 g_wp [384*384];
__device__ __nv_bfloat16 g_w1d[192*384];
__device__ __nv_bfloat16 g_w1u[1536*192];
__device__ __nv_bfloat16 g_w2d[192*1536];
__device__ __nv_bfloat16 g_w2u[384*192];

// ---------------- helpers ----------------------------------------------------
__device__ __forceinline__ unsigned smem_u32(const void* p) {
    unsigned a;
    asm("{ .reg .u64 t; cvta.to.shared.u64 t, %1; cvt.u32.u64 %0, t; }"
        : "=r"(a) : "l"(p));
    return a;
}
__device__ __forceinline__ void cpasync16(unsigned dst, const void* src) {
    asm volatile("cp.async.cg.shared.global [%0], [%1], 16;" :: "r"(dst), "l"(src));
}
#define CP_COMMIT() asm volatile("cp.async.commit_group;" ::: "memory")
__device__ __forceinline__ void ldm_x4(unsigned& r0, unsigned& r1, unsigned& r2,
                                       unsigned& r3, unsigned addr) {
    asm volatile("ldmatrix.sync.aligned.m8n8.x4.shared.b16 {%0,%1,%2,%3}, [%4];"
                 : "=r"(r0), "=r"(r1), "=r"(r2), "=r"(r3) : "r"(addr));
}
__device__ __forceinline__ void mma_bf16(float* d, const unsigned* a,
                                         unsigned b0, unsigned b1) {
    asm volatile(
        "mma.sync.aligned.m16n8k16.row.col.f32.bf16.bf16.f32 "
        "{%0,%1,%2,%3}, {%4,%5,%6,%7}, {%8,%9}, {%0,%1,%2,%3};\n"
        : "+f"(d[0]), "+f"(d[1]), "+f"(d[2]), "+f"(d[3])
        : "r"(a[0]), "r"(a[1]), "r"(a[2]), "r"(a[3]), "r"(b0), "r"(b1));
}
// packed f32x2 (sm_100+ baseline PTX, not arch-'a'-gated)
__device__ __forceinline__ ull fma2(ull a, ull b, ull c) {
    ull d;
    asm("fma.rn.f32x2 %0, %1, %2, %3;" : "=l"(d) : "l"(a), "l"(b), "l"(c));
    return d;
}
__device__ __forceinline__ ull pk(float lo, float hi) {
    ull r;
    asm("mov.b64 %0, {%1, %2};" : "=l"(r) : "f"(lo), "f"(hi));
    return r;
}
__device__ __forceinline__ void unpk(float& lo, float& hi, ull v) {
    asm("mov.b64 {%0, %1}, %2;" : "=f"(lo), "=f"(hi) : "l"(v));
}

#define ASTR 40   // padded row stride (bf16): 32 data + 8 pad -> conflict-free ldmatrix

// ============ bf16 GEMM, 128x128 tile (N % 128 == 0), 3-stage pipeline =======
__global__ __launch_bounds__(256) void bgemm128(
    const __nv_bfloat16* __restrict__ A, const __nv_bfloat16* __restrict__ Bw,
    float* __restrict__ Cf, __nv_bfloat16* __restrict__ Cb,
    int M, int N, int K,
    const float* __restrict__ bias, const float* __restrict__ res, int do_gelu)
{
    __shared__ __align__(16) __nv_bfloat16 As[3][128][ASTR];
    __shared__ __align__(16) __nv_bfloat16 Bs[3][128][ASTR];
    int tid = threadIdx.x, lane = tid & 31, wid = tid >> 5;
    int wm = wid & 1, wn = wid >> 1;
    const __nv_bfloat16* Ab = A  + (size_t)blockIdx.y * 128 * K;
    const __nv_bfloat16* Bb = Bw + (size_t)blockIdx.x * 128 * K;

    float acc[4][4][4];
#pragma unroll
    for (int mf = 0; mf < 4; mf++)
#pragma unroll
        for (int nf = 0; nf < 4; nf++)
#pragma unroll
            for (int i = 0; i < 4; i++) acc[mf][nf][i] = 0.f;

    int nk = K >> 5;
    int lrow = tid >> 2, lseg = tid & 3;

#pragma unroll
    for (int pc = 0; pc < 2; pc++) {
        long kb = (long)pc * 32;
#pragma unroll
        for (int i = 0; i < 2; i++) {
            int row = lrow + i * 64;
            cpasync16(smem_u32(&As[pc][row][lseg * 8]), Ab + (size_t)row * K + kb + lseg * 8);
            cpasync16(smem_u32(&Bs[pc][row][lseg * 8]), Bb + (size_t)row * K + kb + lseg * 8);
        }
        CP_COMMIT();
    }

    for (int kc = 0; kc < nk; kc++) {
        int buf = kc % 3;
        if (kc + 1 < nk) asm volatile("cp.async.wait_group 1;" ::: "memory");
        else             asm volatile("cp.async.wait_group 0;" ::: "memory");
        __syncthreads();
        if (kc + 2 < nk) {
            int nbuf = (kc + 2) % 3;
            long kb = (long)(kc + 2) * 32;
#pragma unroll
            for (int i = 0; i < 2; i++) {
                int row = lrow + i * 64;
                cpasync16(smem_u32(&As[nbuf][row][lseg * 8]),
                          Ab + (size_t)row * K + kb + lseg * 8);
                cpasync16(smem_u32(&Bs[nbuf][row][lseg * 8]),
                          Bb + (size_t)row * K + kb + lseg * 8);
            }
            CP_COMMIT();
        }

#pragma unroll
        for (int ks = 0; ks < 2; ks++) {
            unsigned a[4][4], bb[4][2];
#pragma unroll
            for (int mf = 0; mf < 4; mf++) {
                int r = wm * 64 + mf * 16 + (lane & 15);
                int c = ks * 16 + (lane >> 4) * 8;
                ldm_x4(a[mf][0], a[mf][1], a[mf][2], a[mf][3],
                       smem_u32(&As[buf][r][c]));
            }
#pragma unroll
            for (int nh = 0; nh < 2; nh++) {
                int r = wn * 32 + nh * 16 + (lane >> 4) * 8 + (lane & 7);
                int c = ks * 16 + ((lane >> 3) & 1) * 8;
                unsigned r0, r1, r2, r3;
                ldm_x4(r0, r1, r2, r3, smem_u32(&Bs[buf][r][c]));
                bb[nh * 2][0] = r0; bb[nh * 2][1] = r1;
                bb[nh * 2 + 1][0] = r2; bb[nh * 2 + 1][1] = r3;
            }
#pragma unroll
            for (int mf = 0; mf < 4; mf++)
#pragma unroll
                for (int nf = 0; nf < 4; nf++)
                    mma_bf16(acc[mf][nf], a[mf], bb[nf][0], bb[nf][1]);
        }
    }

    int g = lane >> 2, t = lane & 3;
#pragma unroll
    for (int mf = 0; mf < 4; mf++)
#pragma unroll
        for (int nf = 0; nf < 4; nf++) {
            int col = blockIdx.x * 128 + wn * 32 + nf * 8 + 2 * t;
#pragma unroll
            for (int rr = 0; rr < 2; rr++) {
                int row = blockIdx.y * 128 + wm * 64 + mf * 16 + g + rr * 8;
                float v0 = acc[mf][nf][rr * 2 + 0];
                float v1 = acc[mf][nf][rr * 2 + 1];
                if (bias) { v0 += __ldg(&bias[col]); v1 += __ldg(&bias[col + 1]); }
                if (do_gelu) {
                    v0 = 0.5f * v0 * (1.f + erff(v0 * 0.70710678118f));
                    v1 = 0.5f * v1 * (1.f + erff(v1 * 0.70710678118f));
                }
                if (res) {
                    float2 rv = *(const float2*)(res + (size_t)row * N + col);
                    v0 += rv.x; v1 += rv.y;
                }
                if (Cf) {
                    float2 o; o.x = v0; o.y = v1;
                    *(float2*)(Cf + (size_t)row * N + col) = o;
                } else {
                    __nv_bfloat162 b2 = __floats2bfloat162_rn(v0, v1);
                    *(__nv_bfloat162*)(Cb + (size_t)row * N + col) = b2;
                }
            }
        }
}

// ============ final GEMM: 128x128 tile, N=384, writes NCHW out directly ======
__global__ __launch_bounds__(256) void bgemm128_nchw(
    const __nv_bfloat16* __restrict__ A, const __nv_bfloat16* __restrict__ Bw,
    float* __restrict__ out, int M, int N, int K,
    const float* __restrict__ bias, const float* __restrict__ res)
{
    __shared__ __align__(16) __nv_bfloat16 As[3][128][ASTR];
    __shared__ __align__(16) __nv_bfloat16 Bs[3][128][ASTR];
    __shared__ float tbuf[32][132];
    int tid = threadIdx.x, lane = tid & 31, wid = tid >> 5;
    int wm = wid & 1, wn = wid >> 1;
    const __nv_bfloat16* Ab = A  + (size_t)blockIdx.y * 128 * K;
    const __nv_bfloat16* Bb = Bw + (size_t)blockIdx.x * 128 * K;

    float acc[4][4][4];
#pragma unroll
    for (int mf = 0; mf < 4; mf++)
#pragma unroll
        for (int nf = 0; nf < 4; nf++)
#pragma unroll
            for (int i = 0; i < 4; i++) acc[mf][nf][i] = 0.f;

    int nk = K >> 5;
    int lrow = tid >> 2, lseg = tid & 3;

#pragma unroll
    for (int pc = 0; pc < 2; pc++) {
        long kb = (long)pc * 32;
#pragma unroll
        for (int i = 0; i < 2; i++) {
            int row = lrow + i * 64;
            cpasync16(smem_u32(&As[pc][row][lseg * 8]), Ab + (size_t)row * K + kb + lseg * 8);
            cpasync16(smem_u32(&Bs[pc][row][lseg * 8]), Bb + (size_t)row * K + kb + lseg * 8);
        }
        CP_COMMIT();
    }

    for (int kc = 0; kc < nk; kc++) {
        int buf = kc % 3;
        if (kc + 1 < nk) asm volatile("cp.async.wait_group 1;" ::: "memory");
        else             asm volatile("cp.async.wait_group 0;" ::: "memory");
        __syncthreads();
        if (kc + 2 < nk) {
            int nbuf = (kc + 2) % 3;
            long kb = (long)(kc + 2) * 32;
#pragma unroll
            for (int i = 0; i < 2; i++) {
                int row = lrow + i * 64;
                cpasync16(smem_u32(&As[nbuf][row][lseg * 8]),
                          Ab + (size_t)row * K + kb + lseg * 8);
                cpasync16(smem_u32(&Bs[nbuf][row][lseg * 8]),
                          Bb + (size_t)row * K + kb + lseg * 8);
            }
            CP_COMMIT();
        }

#pragma unroll
        for (int ks = 0; ks < 2; ks++) {
            unsigned a[4][4], bb[4][2];
#pragma unroll
            for (int mf = 0; mf < 4; mf++) {
                int r = wm * 64 + mf * 16 + (lane & 15);
                int c = ks * 16 + (lane >> 4) * 8;
                ldm_x4(a[mf][0], a[mf][1], a[mf][2], a[mf][3],
                       smem_u32(&As[buf][r][c]));
            }
#pragma unroll
            for (int nh = 0; nh < 2; nh++) {
                int r = wn * 32 + nh * 16 + (lane >> 4) * 8 + (lane & 7);
                int c = ks * 16 + ((lane >> 3) & 1) * 8;
                unsigned r0, r1, r2, r3;
                ldm_x4(r0, r1, r2, r3, smem_u32(&Bs[buf][r][c]));
                bb[nh * 2][0] = r0; bb[nh * 2][1] = r1;
                bb[nh * 2 + 1][0] = r2; bb[nh * 2 + 1][1] = r3;
            }
#pragma unroll
            for (int mf = 0; mf < 4; mf++)
#pragma unroll
                for (int nf = 0; nf < 4; nf++)
                    mma_bf16(acc[mf][nf], a[mf], bb[nf][0], bb[nf][1]);
        }
    }

    // epilogue: bias + residual, then transpose through smem, write NCHW
    int g = lane >> 2, t = lane & 3;
    __syncthreads();
#pragma unroll
    for (int p = 0; p < 4; p++) {
        if (wn == p) {
#pragma unroll
            for (int mf = 0; mf < 4; mf++)
#pragma unroll
                for (int nf = 0; nf < 4; nf++) {
                    int lcol = nf * 8 + 2 * t;
                    int col = blockIdx.x * 128 + p * 32 + lcol;
#pragma unroll
                    for (int rr = 0; rr < 2; rr++) {
                        int lrow2 = wm * 64 + mf * 16 + g + rr * 8;
                        int grow = blockIdx.y * 128 + lrow2;
                        float v0 = acc[mf][nf][rr * 2 + 0] + __ldg(&bias[col]);
                        float v1 = acc[mf][nf][rr * 2 + 1] + __ldg(&bias[col + 1]);
                        float2 rv = *(const float2*)(res + (size_t)grow * N + col);
                        v0 += rv.x; v1 += rv.y;
                        tbuf[lcol][lrow2] = v0;
                        tbuf[lcol + 1][lrow2] = v1;
                    }
                }
        }
        __syncthreads();
#pragma unroll
        for (int q = 0; q < 16; q++) {
            int lin = tid + q * 256;
            int ch = lin >> 7, row = lin & 127;
            int tok = blockIdx.y * 128 + row;
            int bb2 = tok / NTOK, n = tok - bb2 * NTOK;
            out[((size_t)bb2 * CDIM + blockIdx.x * 128 + p * 32 + ch) * NTOK + n] =
                tbuf[ch][row];
        }
        __syncthreads();
    }
}

// ============ bf16 GEMM, 128x64 tile (for N = 192), 3-stage pipeline =========
__global__ __launch_bounds__(256) void bgemm(
    const __nv_bfloat16* __restrict__ A, const __nv_bfloat16* __restrict__ Bw,
    float* __restrict__ Cf, __nv_bfloat16* __restrict__ Cb,
    int M, int N, int K,
    const float* __restrict__ bias, const float* __restrict__ res, int do_gelu)
{
    __shared__ __align__(16) __nv_bfloat16 As[3][128][ASTR];
    __shared__ __align__(16) __nv_bfloat16 Bs[3][64][ASTR];
    int tid = threadIdx.x, lane = tid & 31, wid = tid >> 5;
    int wm = wid & 3, wn = wid >> 2;
    const __nv_bfloat16* Ab = A  + (size_t)blockIdx.y * 128 * K;
    const __nv_bfloat16* Bb = Bw + (size_t)blockIdx.x * 64 * K;

    float acc[2][4][4];
#pragma unroll
    for (int mf = 0; mf < 2; mf++)
#pragma unroll
        for (int nf = 0; nf < 4; nf++)
#pragma unroll
            for (int i = 0; i < 4; i++) acc[mf][nf][i] = 0.f;

    int nk = K >> 5;
    int lrow = tid >> 2, lseg = tid & 3;

#pragma unroll
    for (int pc = 0; pc < 2; pc++) {
        long kb = (long)pc * 32;
#pragma unroll
        for (int i = 0; i < 2; i++) {
            int row = lrow + i * 64;
            cpasync16(smem_u32(&As[pc][row][lseg * 8]),
                      Ab + (size_t)row * K + kb + lseg * 8);
        }
        if (lrow < 64)
            cpasync16(smem_u32(&Bs[pc][lrow][lseg * 8]),
                      Bb + (size_t)lrow * K + kb + lseg * 8);
        CP_COMMIT();
    }

    for (int kc = 0; kc < nk; kc++) {
        int buf = kc % 3;
        if (kc + 1 < nk) asm volatile("cp.async.wait_group 1;" ::: "memory");
        else             asm volatile("cp.async.wait_group 0;" ::: "memory");
        __syncthreads();
        if (kc + 2 < nk) {
            int nbuf = (kc + 2) % 3;
            long kb = (long)(kc + 2) * 32;
#pragma unroll
            for (int i = 0; i < 2; i++) {
                int row = lrow + i * 64;
                cpasync16(smem_u32(&As[nbuf][row][lseg * 8]),
                          Ab + (size_t)row * K + kb + lseg * 8);
            }
            if (lrow < 64)
                cpasync16(smem_u32(&Bs[nbuf][lrow][lseg * 8]),
                          Bb + (size_t)lrow * K + kb + lseg * 8);
            CP_COMMIT();
        }

#pragma unroll
        for (int ks = 0; ks < 2; ks++) {
            unsigned a[2][4], bb[4][2];
#pragma unroll
            for (int mf = 0; mf < 2; mf++) {
                int r = wm * 32 + mf * 16 + (lane & 15);
                int c = ks * 16 + (lane >> 4) * 8;
                ldm_x4(a[mf][0], a[mf][1], a[mf][2], a[mf][3],
                       smem_u32(&As[buf][r][c]));
            }
#pragma unroll
            for (int nh = 0; nh < 2; nh++) {
                int r = wn * 32 + nh * 16 + (lane >> 4) * 8 + (lane & 7);
                int c = ks * 16 + ((lane >> 3) & 1) * 8;
                unsigned r0, r1, r2, r3;
                ldm_x4(r0, r1, r2, r3, smem_u32(&Bs[buf][r][c]));
                bb[nh * 2][0] = r0; bb[nh * 2][1] = r1;
                bb[nh * 2 + 1][0] = r2; bb[nh * 2 + 1][1] = r3;
            }
#pragma unroll
            for (int mf = 0; mf < 2; mf++)
#pragma unroll
                for (int nf = 0; nf < 4; nf++)
                    mma_bf16(acc[mf][nf], a[mf], bb[nf][0], bb[nf][1]);
        }
    }

    int g = lane >> 2, t = lane & 3;
#pragma unroll
    for (int mf = 0; mf < 2; mf++)
#pragma unroll
        for (int nf = 0; nf < 4; nf++) {
            int col = blockIdx.x * 64 + wn * 32 + nf * 8 + 2 * t;
#pragma unroll
            for (int rr = 0; rr < 2; rr++) {
                int row = blockIdx.y * 128 + wm * 32 + mf * 16 + g + rr * 8;
                float v0 = acc[mf][nf][rr * 2 + 0];
                float v1 = acc[mf][nf][rr * 2 + 1];
                if (bias) { v0 += __ldg(&bias[col]); v1 += __ldg(&bias[col + 1]); }
                if (do_gelu) {
                    v0 = 0.5f * v0 * (1.f + erff(v0 * 0.70710678118f));
                    v1 = 0.5f * v1 * (1.f + erff(v1 * 0.70710678118f));
                }
                if (res) {
                    float2 rv = *(const float2*)(res + (size_t)row * N + col);
                    v0 += rv.x; v1 += rv.y;
                }
                if (Cf) {
                    float2 o; o.x = v0; o.y = v1;
                    *(float2*)(Cf + (size_t)row * N + col) = o;
                } else {
                    __nv_bfloat162 b2 = __floats2bfloat162_rn(v0, v1);
                    *(__nv_bfloat162*)(Cb + (size_t)row * N + col) = b2;
                }
            }
        }
}

// ---------------- all weight transposes fp32[K,N] -> bf16[N,K], one launch ---
#define WT0 442368
#define WT1 589824
#define WT2 663552
#define WT3 958464
#define WT4 1253376
#define WT5 1327104
__global__ __launch_bounds__(256) void wtrans_all(
    const float* __restrict__ w0, const float* __restrict__ w1,
    const float* __restrict__ w2, const float* __restrict__ w3,
    const float* __restrict__ w4, const float* __restrict__ w5)
{
    int i = blockIdx.x * 256 + threadIdx.x;
    if (i >= WT5) return;
    const float* s; __nv_bfloat16* d; int off, K;
    if      (i < WT0) { s = w0; d = g_wq;  off = 0;   K = 384; }
    else if (i < WT1) { s = w1; d = g_wp;  off = WT0; K = 384; }
    else if (i < WT2) { s = w2; d = g_w1d; off = WT1; K = 384; }
    else if (i < WT3) { s = w3; d = g_w1u; off = WT2; K = 192; }
    else if (i < WT4) { s = w4; d = g_w2d; off = WT3; K = 1536; }
    else              { s = w5; d = g_w2u; off = WT4; K = 192; }
    int j = i - off;
    int n = j / K, k = j - n * K;
    int N = (i < WT0) ? 1152 : (i < WT1) ? 384 : (i < WT2) ? 192 :
            (i < WT3) ? 1536 : (i < WT4) ? 192 : 384;
    d[j] = __float2bfloat16(s[(size_t)k * N + n]);
}

// ---------------- depthwise 3x3 conv (correlation, SAME) --------------------
__global__ __launch_bounds__(256) void dwconv_kernel(
    const float* __restrict__ pA, long strideA,
    const float* __restrict__ pB, long strideB,
    const float* __restrict__ w, const float* __restrict__ bias,
    float* __restrict__ out)
{
    int idx = blockIdx.x * 256 + threadIdx.x;
    if (idx >= Bsz * SPLIT * NTOK) return;
    int n = idx % NTOK;
    int c = (idx / NTOK) % SPLIT;
    int b = idx / (NTOK * SPLIT);
    int hh = n / WW, ww = n % WW;
    const float* a  = pA + (size_t)b * strideA + (size_t)c * NTOK;
    const float* bb = pB + (size_t)b * strideB + (size_t)c * NTOK;
    float acc = bias[c];
#pragma unroll
    for (int i = 0; i < 3; i++) {
        int ih = hh + i - 1;
        if (ih < 0 || ih >= HH) continue;
#pragma unroll
        for (int j = 0; j < 3; j++) {
            int iw = ww + j - 1;
            if (iw < 0 || iw >= WW) continue;
            int off = ih * WW + iw;
            acc += w[c * 9 + i * 3 + j] * (a[off] + bb[off]);
        }
    }
    out[idx] = acc;
}

// ------------- assemble token-major x_flat from s0|s1|s2 (tiled transpose) --
__global__ __launch_bounds__(256) void assemble_kernel(const float* __restrict__ x)
{
    __shared__ float tile[32][33];
    int b = blockIdx.z, c0 = blockIdx.y * 32, n0 = blockIdx.x * 32;
    int tx = threadIdx.x, ty = threadIdx.y;
    const float* src;
    if (c0 < 128)      src = x    + ((size_t)b * CDIM  + c0)        * NTOK;
    else if (c0 < 256) src = g_s1 + ((size_t)b * SPLIT + (c0-128)) * NTOK;
    else               src = g_s2 + ((size_t)b * SPLIT + (c0-256)) * NTOK;
#pragma unroll
    for (int r = 0; r < 4; r++)
        tile[ty + r * 8][tx] = src[(size_t)(ty + r * 8) * NTOK + n0 + tx];
    __syncthreads();
#pragma unroll
    for (int r = 0; r < 4; r++)
        g_xf[((size_t)b * NTOK + n0 + ty + r * 8) * CDIM + c0 + tx] = tile[tx][ty + r * 8];
}

// ---------------- LayerNorm over C=384, bf16 output -------------------------
__global__ __launch_bounds__(128) void ln_kernel(
    const float* __restrict__ src, __nv_bfloat16* __restrict__ dst,
    const float* __restrict__ g, const float* __restrict__ bta)
{
    int tok = blockIdx.x;
    const float* r = src + (size_t)tok * CDIM;
    int tid = threadIdx.x;
    float v0 = r[tid], v1 = r[tid + 128], v2 = r[tid + 256];
    float s  = v0 + v1 + v2;
    float s2 = v0 * v0 + v1 * v1 + v2 * v2;
#pragma unroll
    for (int o = 16; o > 0; o >>= 1) {
        s  += __shfl_down_sync(0xFFFFFFFFu, s,  o);
        s2 += __shfl_down_sync(0xFFFFFFFFu, s2, o);
    }
    __shared__ float ss[4], ss2[4];
    int w = tid >> 5;
    if ((tid & 31) == 0) { ss[w] = s; ss2[w] = s2; }
    __syncthreads();
    if (tid == 0) {
        float a  = ss[0] + ss[1] + ss[2] + ss[3];
        float a2 = ss2[0] + ss2[1] + ss2[2] + ss2[3];
        float m  = a / CDIM;
        float var = a2 / CDIM - m * m;
        ss[0] = m; ss2[0] = rsqrtf(var + 1e-6f);
    }
    __syncthreads();
    float m = ss[0], rs = ss2[0];
    __nv_bfloat16* d = dst + (size_t)tok * CDIM;
    d[tid]       = __float2bfloat16((v0 - m) * rs * g[tid]       + bta[tid]);
    d[tid + 128] = __float2bfloat16((v1 - m) * rs * g[tid + 128] + bta[tid + 128]);
    d[tid + 256] = __float2bfloat16((v2 - m) * rs * g[tid + 256] + bta[tid + 256]);
}

// ---------------- XCA attention, kernel A: partial Gram + sumsq -------------
__global__ __launch_bounds__(256) void attn_gram()
{
    const __nv_bfloat16* qkv16 = (const __nv_bfloat16*)g_big;
    int s = blockIdx.x, h = blockIdx.y, b = blockIdx.z;
    __shared__ float q_s[48][66];
    __shared__ float k_s[48][66];
    int tid = threadIdx.x;
    int td = tid >> 4, te = tid & 15;

    ull acc2[3][3];
#pragma unroll
    for (int i = 0; i < 3; i++)
#pragma unroll
        for (int j = 0; j < 3; j++) acc2[i][j] = 0ULL;
    float qssl = 0.f, kssl = 0.f;

    for (int t = 0; t < 7; t++) {
        int n0 = (s * 7 + t) * 64;
        for (int i = tid; i < 48 * 64; i += 256) {
            int d = i % 48, nn = i / 48;
            size_t base = ((size_t)(b * NTOK + n0 + nn)) * 1152 + h * 48 + d;
            q_s[d][nn] = __bfloat162float(qkv16[base]);
            k_s[d][nn] = __bfloat162float(qkv16[base + 384]);
        }
        __syncthreads();
        if (tid < 48) {
            float tt = 0.f;
#pragma unroll 8
            for (int nn = 0; nn < 64; nn++) { float vv = q_s[tid][nn]; tt += vv * vv; }
            qssl += tt;
        } else if (tid >= 64 && tid < 112) {
            int d = tid - 64;
            float tt = 0.f;
#pragma unroll 8
            for (int nn = 0; nn < 64; nn++) { float vv = k_s[d][nn]; tt += vv * vv; }
            kssl += tt;
        }
#pragma unroll 4
        for (int nn2 = 0; nn2 < 32; nn2++) {
            ull q2[3], k2[3];
#pragma unroll
            for (int i = 0; i < 3; i++)
                q2[i] = *(const ull*)&q_s[td * 3 + i][2 * nn2];
#pragma unroll
            for (int j = 0; j < 3; j++)
                k2[j] = *(const ull*)&k_s[te * 3 + j][2 * nn2];
#pragma unroll
            for (int i = 0; i < 3; i++)
#pragma unroll
                for (int j = 0; j < 3; j++)
                    acc2[i][j] = fma2(q2[i], k2[j], acc2[i][j]);
        }
        __syncthreads();
    }
    int bh = b * 8 + h;
    size_t gbase = ((size_t)(s * 128 + bh)) * 2304;
#pragma unroll
    for (int i = 0; i < 3; i++)
#pragma unroll
        for (int j = 0; j < 3; j++) {
            float lo, hi;
            unpk(lo, hi, acc2[i][j]);
            g_gramP[gbase + (td * 3 + i) * 48 + te * 3 + j] = lo + hi;
        }
    if (tid < 48)                 g_qsqP[(size_t)(s * 128 + bh) * 48 + tid] = qssl;
    if (tid >= 64 && tid < 112)   g_ksqP[(size_t)(s * 128 + bh) * 48 + tid - 64] = kssl;
}

// ---------------- kernel B: reduce partials, softmax, pre-replicate ---------
__global__ __launch_bounds__(64) void attn_soft()
{
    int h = blockIdx.x, b = blockIdx.y;
    int bh = b * 8 + h;
    __shared__ float qn[48], kn[48];
    int tid = threadIdx.x;
    if (tid < 48) {
        float q = 0.f, k = 0.f;
#pragma unroll
        for (int s = 0; s < NSPL; s++) {
            q += g_qsqP[(size_t)(s * 128 + bh) * 48 + tid];
            k += g_ksqP[(size_t)(s * 128 + bh) * 48 + tid];
        }
        qn[tid] = fmaxf(sqrtf(q), 1e-12f);
        kn[tid] = fmaxf(sqrtf(k), 1e-12f);
    }
    __syncthreads();
    if (tid < 48) {
        int r = tid;
        float vals[48];
        float iq = 1.f / qn[r];
#pragma unroll 8
        for (int e = 0; e < 48; e++) {
            float gsum = 0.f;
#pragma unroll
            for (int s = 0; s < NSPL; s++)
                gsum += g_gramP[((size_t)(s * 128 + bh)) * 2304 + r * 48 + e];
            vals[e] = gsum * iq / kn[e];
        }
        float mx = -1e30f;
#pragma unroll 8
        for (int e = 0; e < 48; e++) mx = fmaxf(mx, vals[e]);
        float sm = 0.f;
#pragma unroll 8
        for (int e = 0; e < 48; e++) { vals[e] = expf(vals[e] - mx); sm += vals[e]; }
        float inv = 1.f / sm;
        float2* dst = g_attn2 + (size_t)bh * 2304 + r * 48;
#pragma unroll 8
        for (int e = 0; e < 48; e++) {
            float p = vals[e] * inv;
            dst[e] = make_float2(p, p);
        }
    }
}

// ---------------- kernel C: y = attn @ V, f32x2, 2 tokens/lane --------------
__global__ __launch_bounds__(256) void attn_apply()
{
    const __nv_bfloat16* qkv16 = (const __nv_bfloat16*)g_big;
    int s = blockIdx.x, h = blockIdx.y, b = blockIdx.z;
    __shared__ float2 a2s[2304];
    int tid = threadIdx.x, lane = tid & 31, wid = tid >> 5;
    const float2* gsrc = g_attn2 + (size_t)(b * 8 + h) * 2304;
    for (int i = tid; i < 2304; i += 256) a2s[i] = gsrc[i];
    __syncthreads();

    int wt = s * 8 + wid;
    if (wt >= 49) return;
    int tA = wt * 64 + lane, tB = tA + 32;

    const uint4* vpA = (const uint4*)(qkv16 + ((size_t)(b * NTOK + tA)) * 1152 + 768 + h * 48);
    const uint4* vpB = (const uint4*)(qkv16 + ((size_t)(b * NTOK + tB)) * 1152 + 768 + h * 48);
    ull v2[48];
#pragma unroll
    for (int i = 0; i < 6; i++) {
        uint4 ta = vpA[i], tb = vpB[i];
        unsigned wa[4] = { ta.x, ta.y, ta.z, ta.w };
        unsigned wb[4] = { tb.x, tb.y, tb.z, tb.w };
#pragma unroll
        for (int q = 0; q < 4; q++) {
            float2 fa = __bfloat1622float2(*(__nv_bfloat162*)&wa[q]);
            float2 fb = __bfloat1622float2(*(__nv_bfloat162*)&wb[q]);
            v2[i * 8 + q * 2 + 0] = pk(fa.x, fb.x);
            v2[i * 8 + q * 2 + 1] = pk(fa.y, fb.y);
        }
    }

#pragma unroll
    for (int half = 0; half < 2; half++) {
        float oA[24], oB[24];
#pragma unroll
        for (int d = 0; d < 24; d++) {
            int dd = half * 24 + d;
            ull acc = 0ULL;
            const longlong2* ap = (const longlong2*)&a2s[dd * 48];
#pragma unroll
            for (int e2 = 0; e2 < 24; e2++) {
                longlong2 av = ap[e2];
                acc = fma2((ull)av.x, v2[2 * e2], acc);
                acc = fma2((ull)av.y, v2[2 * e2 + 1], acc);
            }
            unpk(oA[d], oB[d], acc);
        }
        __nv_bfloat16* pA = g_att16 + ((size_t)(b * NTOK + tA)) * CDIM + h * 48 + half * 24;
        __nv_bfloat16* pB = g_att16 + ((size_t)(b * NTOK + tB)) * CDIM + h * 48 + half * 24;
        unsigned wA[12], wB[12];
#pragma unroll
        for (int j = 0; j < 12; j++) {
            __nv_bfloat162 xa = __floats2bfloat162_rn(oA[2 * j], oA[2 * j + 1]);
            __nv_bfloat162 xb = __floats2bfloat162_rn(oB[2 * j], oB[2 * j + 1]);
            wA[j] = *(unsigned*)&xa; wB[j] = *(unsigned*)&xb;
        }
#pragma unroll
        for (int j = 0; j < 3; j++) {
            uint4 oa; oa.x = wA[4*j]; oa.y = wA[4*j+1]; oa.z = wA[4*j+2]; oa.w = wA[4*j+3];
            uint4 ob; ob.x = wB[4*j]; ob.y = wB[4*j+1]; ob.z = wB[4*j+2]; ob.w = wB[4*j+3];
            ((uint4*)pA)[j] = oa;
            ((uint4*)pB)[j] = ob;
        }
    }
}

// ---------------------------------------------------------------------------
extern "C" void kernel_launch(void* const* d_in, const int* in_sizes, int n_in,
                              void* d_out, int out_size)
{
    const float* x       = (const float*)d_in[0];
    const float* dw_w0   = (const float*)d_in[1];
    const float* dw_b0   = (const float*)d_in[2];
    const float* dw_w1   = (const float*)d_in[3];
    const float* dw_b1   = (const float*)d_in[4];
    const float* ln1_g   = (const float*)d_in[5];
    const float* ln1_b   = (const float*)d_in[6];
    const float* qkv_w   = (const float*)d_in[7];
    const float* proj_w  = (const float*)d_in[8];
    const float* proj_b  = (const float*)d_in[9];
    const float* ln2_g   = (const float*)d_in[10];
    const float* ln2_b   = (const float*)d_in[11];
    const float* mlp1_dw = (const float*)d_in[12];
    const float* mlp1_uw = (const float*)d_in[13];
    const float* mlp1_ub = (const float*)d_in[14];
    const float* mlp2_dw = (const float*)d_in[15];
    const float* mlp2_uw = (const float*)d_in[16];
    const float* mlp2_ub = (const float*)d_in[17];
    float* out = (float*)d_out;

    float *big, *s1, *s2, *xf, *xf2;
    __nv_bfloat16 *y16, *att16, *t116, *t216, *h16;
    __nv_bfloat16 *wq, *wp, *w1d, *w1u, *w2d, *w2u;
    cudaGetSymbolAddress((void**)&big,  g_big);
    cudaGetSymbolAddress((void**)&s1,   g_s1);
    cudaGetSymbolAddress((void**)&s2,   g_s2);
    cudaGetSymbolAddress((void**)&xf,   g_xf);
    cudaGetSymbolAddress((void**)&xf2,  g_xf2);
    cudaGetSymbolAddress((void**)&y16,  g_y16);
    cudaGetSymbolAddress((void**)&att16,g_att16);
    cudaGetSymbolAddress((void**)&t116, g_t116);
    cudaGetSymbolAddress((void**)&t216, g_t216);
    cudaGetSymbolAddress((void**)&h16,  g_h16);
    cudaGetSymbolAddress((void**)&wq,   g_wq);
    cudaGetSymbolAddress((void**)&wp,   g_wp);
    cudaGetSymbolAddress((void**)&w1d,  g_w1d);
    cudaGetSymbolAddress((void**)&w1u,  g_w1u);
    cudaGetSymbolAddress((void**)&w2d,  g_w2d);
    cudaGetSymbolAddress((void**)&w2u,  g_w2u);
    __nv_bfloat16* qkv16 = (__nv_bfloat16*)big;

    wtrans_all<<<(WT5 + 255) / 256, 256>>>(qkv_w, proj_w, mlp1_dw, mlp1_uw,
                                           mlp2_dw, mlp2_uw);

    int nconv = Bsz * SPLIT * NTOK;
    int cblk = (nconv + 255) / 256;

    dwconv_kernel<<<cblk, 256>>>(x, (long)CDIM * NTOK,
                                 x + (size_t)SPLIT * NTOK, (long)CDIM * NTOK,
                                 dw_w0, dw_b0, s1);
    dwconv_kernel<<<cblk, 256>>>(s1, (long)SPLIT * NTOK,
                                 x + (size_t)2 * SPLIT * NTOK, (long)CDIM * NTOK,
                                 dw_w1, dw_b1, s2);

    assemble_kernel<<<dim3(98, 12, Bsz), dim3(32, 8)>>>(x);

    ln_kernel<<<TOKS, 128>>>(xf, y16, ln1_g, ln1_b);

    // qkv = y @ qkv_w (bf16 out into g_big alias)
    bgemm128<<<dim3(1152/128, TOKS/128), 256>>>(y16, wq, nullptr, qkv16,
                                                TOKS, 1152, 384, nullptr, nullptr, 0);

    // attention: gram partials -> softmax -> apply
    attn_gram<<<dim3(NSPL, NHEAD, Bsz), 256>>>();
    attn_soft<<<dim3(NHEAD, Bsz), 64>>>();
    attn_apply<<<dim3(NSPL, NHEAD, Bsz), 256>>>();

    // xf2 = xf + att @ proj_w + proj_b
    bgemm128<<<dim3(384/128, TOKS/128), 256>>>(att16, wp, xf2, nullptr,
                                               TOKS, 384, 384, proj_b, xf, 0);

    ln_kernel<<<TOKS, 128>>>(xf2, y16, ln2_g, ln2_b);

    bgemm<<<dim3(192/64, TOKS/128), 256>>>(y16, w1d, nullptr, t116,
                                           TOKS, 192, 384, nullptr, nullptr, 0);
    bgemm128<<<dim3(1536/128, TOKS/128), 256>>>(t116, w1u, nullptr, h16,
                                                TOKS, 1536, 192, mlp1_ub, nullptr, 1);
    bgemm<<<dim3(192/64, TOKS/128), 256>>>(h16, w2d, nullptr, t216,
                                           TOKS, 192, 1536, nullptr, nullptr, 0);
    // final: out(NCHW) = xf2 + t2 @ mlp2_uw + b, fused transpose
    bgemm128_nchw<<<dim3(384/128, TOKS/128), 256>>>(t216, w2u, out,
                                                    TOKS, 384, 192, mlp2_ub, xf2);

    (void)in_sizes; (void)n_in; (void)out_size;
}